// round 7
// baseline (speedup 1.0000x reference)
#include <cuda_runtime.h>
#include <cstdint>

#define Nn 50000
#define Ee 800000
#define FIN 256
#define F1 32
#define H1 8
#define NHID 256
#define NC 47

// ---------------- scratch (device globals: allocation-free) ----------------
__device__ int   g_rowptr[Nn + 1];
__device__ int   g_cursor[Nn];
__device__ int   g_csr_dst[Ee];
__device__ int   g_bsums[64];
__device__ float g_h1[Nn * F1];          // 6.4 MB  (L2 resident)
__device__ float g_el1[Nn * H1];
__device__ float g_er1[Nn * H1];
__device__ float g_r1[Nn * NHID];        // 51.2 MB
__device__ float g_h2p[Nn * 48];         // padded h2 (48 cols), 9.6 MB
__device__ float g_el2[Nn];
__device__ float g_er2[Nn];
__device__ float g_B1ext[FIN * 48];      // [W1 | W1@Wl1 | W1@Wr1]
__device__ float g_B2ext[FIN * 50];      // [W2 | 0pad | W2@Wl2 | W2@Wr2]

// ---------------- tf32 mma helpers ----------------
__device__ __forceinline__ uint32_t f2tf32(float f) {
    uint32_t r;
    asm("cvt.rna.tf32.f32 %0, %1;" : "=r"(r) : "f"(f));
    return r;
}

__device__ __forceinline__ void mma_tf32(float* d,
    uint32_t a0, uint32_t a1, uint32_t a2, uint32_t a3,
    uint32_t b0, uint32_t b1) {
    asm volatile(
        "mma.sync.aligned.m16n8k8.row.col.f32.tf32.tf32.f32 "
        "{%0,%1,%2,%3},{%4,%5,%6,%7},{%8,%9},{%0,%1,%2,%3};\n"
        : "+f"(d[0]), "+f"(d[1]), "+f"(d[2]), "+f"(d[3])
        : "r"(a0), "r"(a1), "r"(a2), "r"(a3), "r"(b0), "r"(b1));
}

// ---------------- init: preps + zero counts (fused) ----------------
__global__ void k_init(const float* __restrict__ W1, const float* __restrict__ Wl1,
                       const float* __restrict__ Wr1, const float* __restrict__ W2,
                       const float* __restrict__ Wl2, const float* __restrict__ Wr2) {
    int b = blockIdx.x;
    int k = threadIdx.x;
    if (b == 0) {                       // prep1
        __shared__ float swl[F1 * H1], swr[F1 * H1];
        swl[k] = Wl1[k];
        swr[k] = Wr1[k];
        __syncthreads();
        float row[F1];
        #pragma unroll
        for (int j = 0; j < F1; j++) row[j] = W1[k * F1 + j];
        #pragma unroll
        for (int j = 0; j < F1; j++) g_B1ext[k * 48 + j] = row[j];
        #pragma unroll
        for (int h = 0; h < H1; h++) {
            float sl = 0.f, sr = 0.f;
            #pragma unroll
            for (int j = 0; j < F1; j++) {
                sl = fmaf(row[j], swl[j * H1 + h], sl);
                sr = fmaf(row[j], swr[j * H1 + h], sr);
            }
            g_B1ext[k * 48 + 32 + h] = sl;
            g_B1ext[k * 48 + 40 + h] = sr;
        }
    } else if (b == 1) {                // prep2
        __shared__ float swl2[NC], swr2[NC];
        if (k < NC) { swl2[k] = Wl2[k]; swr2[k] = Wr2[k]; }
        __syncthreads();
        float row[NC];
        #pragma unroll
        for (int j = 0; j < NC; j++) row[j] = W2[k * NC + j];
        #pragma unroll
        for (int j = 0; j < NC; j++) g_B2ext[k * 50 + j] = row[j];
        g_B2ext[k * 50 + 47] = 0.f;
        float sl = 0.f, sr = 0.f;
        #pragma unroll
        for (int j = 0; j < NC; j++) {
            sl = fmaf(row[j], swl2[j], sl);
            sr = fmaf(row[j], swr2[j], sr);
        }
        g_B2ext[k * 50 + 48] = sl;
        g_B2ext[k * 50 + 49] = sr;
    } else {                            // zero rowptr
        int i = (b - 2) * 256 + k;
        if (i < Nn + 1) g_rowptr[i] = 0;
    }
}

// ---------------- CSR build ----------------
__global__ void k_count(const int* __restrict__ src) {
    int e = blockIdx.x * blockDim.x + threadIdx.x;
    if (e < Ee) atomicAdd(&g_rowptr[src[e]], 1);
}

__global__ void k_scan_blocks(int n) {
    __shared__ int wsum[32];
    int tid = threadIdx.x;
    int gid = blockIdx.x * 1024 + tid;
    int v = (gid < n) ? g_rowptr[gid] : 0;
    int lane = tid & 31, wid = tid >> 5;
    int x = v;
    #pragma unroll
    for (int d = 1; d < 32; d <<= 1) {
        int t = __shfl_up_sync(0xffffffffu, x, d);
        if (lane >= d) x += t;
    }
    if (lane == 31) wsum[wid] = x;
    __syncthreads();
    if (wid == 0) {
        int w = wsum[lane];
        #pragma unroll
        for (int d = 1; d < 32; d <<= 1) {
            int t = __shfl_up_sync(0xffffffffu, w, d);
            if (lane >= d) w += t;
        }
        wsum[lane] = w;
    }
    __syncthreads();
    int incl = x + (wid > 0 ? wsum[wid - 1] : 0);
    if (gid < n) g_rowptr[gid] = incl - v;   // exclusive
    if (tid == 1023) g_bsums[blockIdx.x] = incl;
}

__global__ void k_finalize_scan(int n) {
    __shared__ int soff;
    int tid = threadIdx.x;
    if (tid < 32) {
        int v1 = (tid      < (int)blockIdx.x) ? g_bsums[tid]      : 0;
        int v2 = (tid + 32 < (int)blockIdx.x) ? g_bsums[tid + 32] : 0;
        int s = v1 + v2;
        #pragma unroll
        for (int d = 16; d > 0; d >>= 1) s += __shfl_xor_sync(0xffffffffu, s, d);
        if (tid == 0) soff = s;
    }
    __syncthreads();
    int gid = blockIdx.x * 1024 + tid;
    if (gid < n) {
        int v = g_rowptr[gid] + soff;
        g_rowptr[gid] = v;
        if (gid < Nn) g_cursor[gid] = v;
    }
}

__global__ void k_scatter(const int* __restrict__ src, const int* __restrict__ dst) {
    int e = blockIdx.x * blockDim.x + threadIdx.x;
    if (e < Ee) {
        int s = src[e];
        int pos = atomicAdd(&g_cursor[s], 1);
        g_csr_dst[pos] = dst[e];
    }
}

// ---------------- GEMM1 (tf32, N-split over blockIdx.y) ----------------
// blockIdx.y=0: n-tiles 0..2 (h1 cols 0..23); y=1: tiles 3..5 (h1 24..31, el1, er1)
#define S1 26
__global__ void __launch_bounds__(256) k_gemm1(const float* __restrict__ x) {
    extern __shared__ uint32_t sm1[];
    uint32_t* sB = sm1;                      // [256][S1]
    int tx = threadIdx.x, lane = tx & 31, w = tx >> 5;
    int yb = blockIdx.y * 24;
    for (int i = tx; i < FIN * 24; i += 256) {
        int k = i / 24, n = i - k * 24;
        sB[k * S1 + n] = f2tf32(g_B1ext[k * 48 + yb + n]);
    }
    __syncthreads();

    int g = lane >> 2, c = lane & 3;
    int row0 = blockIdx.x * 128 + w * 16 + g;
    int row1 = row0 + 8;
    bool v0 = row0 < Nn, v1 = row1 < Nn;
    const float4* A0 = (const float4*)(x + (size_t)row0 * FIN);
    const float4* A1 = (const float4*)(x + (size_t)row1 * FIN);
    const float4 z4 = make_float4(0.f, 0.f, 0.f, 0.f);

    float acc[3][4];
    #pragma unroll
    for (int nt = 0; nt < 3; nt++)
        #pragma unroll
        for (int j = 0; j < 4; j++) acc[nt][j] = 0.f;

    float4 b0[4], b1[4];
    #pragma unroll
    for (int t = 0; t < 4; t++) {
        b0[t] = v0 ? A0[t * 4 + c] : z4;
        b1[t] = v1 ? A1[t * 4 + c] : z4;
    }
    #pragma unroll
    for (int ch = 0; ch < 4; ch++) {
        float4 n0[4], n1[4];
        #pragma unroll
        for (int t = 0; t < 4; t++) {
            n0[t] = (v0 && ch < 3) ? A0[(ch + 1) * 16 + t * 4 + c] : z4;
            n1[t] = (v1 && ch < 3) ? A1[(ch + 1) * 16 + t * 4 + c] : z4;
        }
        #pragma unroll
        for (int t = 0; t < 4; t++) {
            int wnd = ch * 4 + t;
            uint32_t a00 = f2tf32(b0[t].x), a01 = f2tf32(b0[t].y), a02 = f2tf32(b0[t].z), a03 = f2tf32(b0[t].w);
            uint32_t a10 = f2tf32(b1[t].x), a11 = f2tf32(b1[t].y), a12 = f2tf32(b1[t].z), a13 = f2tf32(b1[t].w);
            const uint32_t* bA = sB + (wnd * 16 + 4 * c) * S1;
            #pragma unroll
            for (int nt = 0; nt < 3; nt++)
                mma_tf32(acc[nt], a00, a10, a01, a11, bA[nt * 8 + g], bA[S1 + nt * 8 + g]);
            #pragma unroll
            for (int nt = 0; nt < 3; nt++)
                mma_tf32(acc[nt], a02, a12, a03, a13, bA[2 * S1 + nt * 8 + g], bA[3 * S1 + nt * 8 + g]);
        }
        #pragma unroll
        for (int t = 0; t < 4; t++) { b0[t] = n0[t]; b1[t] = n1[t]; }
    }
    #pragma unroll
    for (int nt = 0; nt < 3; nt++) {
        int ntg = blockIdx.y * 3 + nt;
        int col = ntg * 8 + 2 * c;
        if (ntg < 4) {
            if (v0) *(float2*)&g_h1[row0 * F1 + col] = make_float2(acc[nt][0], acc[nt][1]);
            if (v1) *(float2*)&g_h1[row1 * F1 + col] = make_float2(acc[nt][2], acc[nt][3]);
        } else if (ntg == 4) {
            if (v0) *(float2*)&g_el1[row0 * H1 + 2 * c] = make_float2(acc[nt][0], acc[nt][1]);
            if (v1) *(float2*)&g_el1[row1 * H1 + 2 * c] = make_float2(acc[nt][2], acc[nt][3]);
        } else {
            if (v0) *(float2*)&g_er1[row0 * H1 + 2 * c] = make_float2(acc[nt][0], acc[nt][1]);
            if (v1) *(float2*)&g_er1[row1 * H1 + 2 * c] = make_float2(acc[nt][2], acc[nt][3]);
        }
    }
}

// ---------------- GEMM2 (tf32, N-split over blockIdx.y) ----------------
// y=0: cols 0..31 of h2p; y=1: cols 32..47 h2p + 48 el2 + 49 er2 (+pad).
#define S2 34
__global__ void __launch_bounds__(256) k_gemm2() {
    extern __shared__ uint32_t sm2[];
    uint32_t* sB = sm2;                      // [256][S2]
    int tx = threadIdx.x, lane = tx & 31, w = tx >> 5;
    int yb = blockIdx.y * 32;
    for (int i = tx; i < FIN * 32; i += 256) {
        int k = i >> 5, n = i & 31;
        int col = yb + n;
        sB[k * S2 + n] = (col < 50) ? f2tf32(g_B2ext[k * 50 + col]) : 0u;
    }
    __syncthreads();

    int g = lane >> 2, c = lane & 3;
    int row0 = blockIdx.x * 128 + w * 16 + g;
    int row1 = row0 + 8;
    bool v0 = row0 < Nn, v1 = row1 < Nn;
    const float4* A0 = (const float4*)(g_r1 + (size_t)row0 * FIN);
    const float4* A1 = (const float4*)(g_r1 + (size_t)row1 * FIN);
    const float4 z4 = make_float4(0.f, 0.f, 0.f, 0.f);

    float acc[4][4];
    #pragma unroll
    for (int nt = 0; nt < 4; nt++)
        #pragma unroll
        for (int j = 0; j < 4; j++) acc[nt][j] = 0.f;

    float4 b0[4], b1[4];
    #pragma unroll
    for (int t = 0; t < 4; t++) {
        b0[t] = v0 ? A0[t * 4 + c] : z4;
        b1[t] = v1 ? A1[t * 4 + c] : z4;
    }
    #pragma unroll
    for (int ch = 0; ch < 4; ch++) {
        float4 n0[4], n1[4];
        #pragma unroll
        for (int t = 0; t < 4; t++) {
            n0[t] = (v0 && ch < 3) ? A0[(ch + 1) * 16 + t * 4 + c] : z4;
            n1[t] = (v1 && ch < 3) ? A1[(ch + 1) * 16 + t * 4 + c] : z4;
        }
        #pragma unroll
        for (int t = 0; t < 4; t++) {
            int wnd = ch * 4 + t;
            uint32_t a00 = f2tf32(b0[t].x), a01 = f2tf32(b0[t].y), a02 = f2tf32(b0[t].z), a03 = f2tf32(b0[t].w);
            uint32_t a10 = f2tf32(b1[t].x), a11 = f2tf32(b1[t].y), a12 = f2tf32(b1[t].z), a13 = f2tf32(b1[t].w);
            const uint32_t* bA = sB + (wnd * 16 + 4 * c) * S2;
            #pragma unroll
            for (int nt = 0; nt < 4; nt++)
                mma_tf32(acc[nt], a00, a10, a01, a11, bA[nt * 8 + g], bA[S2 + nt * 8 + g]);
            #pragma unroll
            for (int nt = 0; nt < 4; nt++)
                mma_tf32(acc[nt], a02, a12, a03, a13, bA[2 * S2 + nt * 8 + g], bA[3 * S2 + nt * 8 + g]);
        }
        #pragma unroll
        for (int t = 0; t < 4; t++) { b0[t] = n0[t]; b1[t] = n1[t]; }
    }
    #pragma unroll
    for (int nt = 0; nt < 4; nt++) {
        int col = blockIdx.y * 32 + nt * 8 + 2 * c;
        if (col < 48) {
            if (v0) *(float2*)&g_h2p[(size_t)row0 * 48 + col] = make_float2(acc[nt][0], acc[nt][1]);
            if (v1) *(float2*)&g_h2p[(size_t)row1 * 48 + col] = make_float2(acc[nt][2], acc[nt][3]);
        } else if (col == 48) {
            if (v0) { g_el2[row0] = acc[nt][0]; g_er2[row0] = acc[nt][1]; }
            if (v1) { g_el2[row1] = acc[nt][2]; g_er2[row1] = acc[nt][3]; }
        }
    }
}

// ---------------- layer-1 aggregation (2 warps/node, 8-edge batches) ----------------
__global__ void k_agg1(const float* __restrict__ b1) {
    __shared__ float ws[8][64];        // [warp][edge(8)][head(8)]
    __shared__ float pacc[4][256];     // [slot][h*32+lane]
    __shared__ float pden[4][256];
    int wid = threadIdx.x >> 5, lane = threadIdx.x & 31;
    int slot = wid >> 1, half = wid & 1;
    int i = blockIdx.x * 4 + slot;

    float el_own = (lane < H1) ? g_el1[i * H1 + lane] : 0.f;
    float elh[H1];
    #pragma unroll
    for (int h = 0; h < H1; h++) elh[h] = __shfl_sync(0xffffffffu, el_own, h);

    float acc[H1], denp[H1];
    #pragma unroll
    for (int h = 0; h < H1; h++) { acc[h] = 0.f; denp[h] = 0.f; }

    int beg = g_rowptr[i], end = g_rowptr[i + 1];
    for (int base = beg + half * 8; base < end; base += 16) {
        int nb = min(8, end - base);
        int dstl = (lane < nb) ? g_csr_dst[base + lane] : 0;
        float w_own[H1];
        if (lane < nb) {
            const float4* er4 = (const float4*)(g_er1 + (size_t)dstl * H1);
            float4 ea = er4[0], eb = er4[1];
            float er_[H1] = {ea.x, ea.y, ea.z, ea.w, eb.x, eb.y, eb.z, eb.w};
            #pragma unroll
            for (int h = 0; h < H1; h++) {
                float a = elh[h] + er_[h];
                float lr = a > 0.f ? a : 0.2f * a;
                float wv = __expf(lr);
                w_own[h] = wv;
                denp[h] += wv;
            }
        } else {
            #pragma unroll
            for (int h = 0; h < H1; h++) w_own[h] = 0.f;
        }
        if (lane < 8) {
            float4* wrow = (float4*)&ws[wid][lane * 8];
            wrow[0] = make_float4(w_own[0], w_own[1], w_own[2], w_own[3]);
            wrow[1] = make_float4(w_own[4], w_own[5], w_own[6], w_own[7]);
        }
        __syncwarp();
        // 8 edges, 2 groups of 4 independent gathers (tail lanes: w=0, dst=0)
        #pragma unroll
        for (int j = 0; j < 8; j += 4) {
            int d0 = __shfl_sync(0xffffffffu, dstl, j);
            int d1 = __shfl_sync(0xffffffffu, dstl, j + 1);
            int d2 = __shfl_sync(0xffffffffu, dstl, j + 2);
            int d3 = __shfl_sync(0xffffffffu, dstl, j + 3);
            float hv0 = g_h1[d0 * F1 + lane];
            float hv1 = g_h1[d1 * F1 + lane];
            float hv2 = g_h1[d2 * F1 + lane];
            float hv3 = g_h1[d3 * F1 + lane];
            const float4* wj = (const float4*)&ws[wid][j * 8];
            #pragma unroll
            for (int u = 0; u < 4; u++) {
                float hv = (u == 0) ? hv0 : (u == 1) ? hv1 : (u == 2) ? hv2 : hv3;
                float4 wa = wj[u * 2], wb = wj[u * 2 + 1];
                acc[0] = fmaf(wa.x, hv, acc[0]);
                acc[1] = fmaf(wa.y, hv, acc[1]);
                acc[2] = fmaf(wa.z, hv, acc[2]);
                acc[3] = fmaf(wa.w, hv, acc[3]);
                acc[4] = fmaf(wb.x, hv, acc[4]);
                acc[5] = fmaf(wb.y, hv, acc[5]);
                acc[6] = fmaf(wb.z, hv, acc[6]);
                acc[7] = fmaf(wb.w, hv, acc[7]);
            }
        }
        __syncwarp();
    }
    if (half == 1) {
        #pragma unroll
        for (int h = 0; h < H1; h++) {
            pacc[slot][h * 32 + lane] = acc[h];
            pden[slot][h * 32 + lane] = denp[h];
        }
    }
    __syncthreads();
    if (half == 0) {
        float bb = b1[lane];
        #pragma unroll
        for (int h = 0; h < H1; h++) {
            acc[h]  += pacc[slot][h * 32 + lane];
            float t = denp[h] + pden[slot][h * 32 + lane];
            #pragma unroll
            for (int d = 16; d > 0; d >>= 1) t += __shfl_xor_sync(0xffffffffu, t, d);
            float o = acc[h] / fmaxf(t, 1e-12f) + bb;
            float e = o > 0.f ? o : (__expf(o) - 1.f);   // ELU
            g_r1[(size_t)i * NHID + h * F1 + lane] = e;
        }
    }
}

// ---------------- layer-2 aggregation (2 warps/node) + log_softmax ----------------
__global__ void k_agg2(const float* __restrict__ b2, float* __restrict__ out) {
    __shared__ float pacc[4][64];
    __shared__ float pden[4][32];
    int wid = threadIdx.x >> 5, lane = threadIdx.x & 31;
    int slot = wid >> 1, half = wid & 1;
    int i = blockIdx.x * 4 + slot;
    float el = g_el2[i];
    float accx = 0.f, accy = 0.f, denp = 0.f;
    int beg = g_rowptr[i], end = g_rowptr[i + 1];
    for (int base = beg + half * 8; base < end; base += 16) {
        int nb = min(8, end - base);
        int dstl = (lane < nb) ? g_csr_dst[base + lane] : 0;
        float wl_ = 0.f;
        if (lane < nb) {
            float a = el + g_er2[dstl];
            float lr = a > 0.f ? a : 0.2f * a;
            wl_ = __expf(lr);
            denp += wl_;
        }
        #pragma unroll
        for (int j = 0; j < 8; j += 4) {
            int   d0 = __shfl_sync(0xffffffffu, dstl, j);
            int   d1 = __shfl_sync(0xffffffffu, dstl, j + 1);
            int   d2 = __shfl_sync(0xffffffffu, dstl, j + 2);
            int   d3 = __shfl_sync(0xffffffffu, dstl, j + 3);
            float w0 = __shfl_sync(0xffffffffu, wl_, j);
            float w1 = __shfl_sync(0xffffffffu, wl_, j + 1);
            float w2 = __shfl_sync(0xffffffffu, wl_, j + 2);
            float w3 = __shfl_sync(0xffffffffu, wl_, j + 3);
            if (lane < 24) {
                float2 h0 = *(const float2*)&g_h2p[(size_t)d0 * 48 + 2 * lane];
                float2 h1_ = *(const float2*)&g_h2p[(size_t)d1 * 48 + 2 * lane];
                float2 h2_ = *(const float2*)&g_h2p[(size_t)d2 * 48 + 2 * lane];
                float2 h3 = *(const float2*)&g_h2p[(size_t)d3 * 48 + 2 * lane];
                accx = fmaf(w0, h0.x, accx);  accy = fmaf(w0, h0.y, accy);
                accx = fmaf(w1, h1_.x, accx); accy = fmaf(w1, h1_.y, accy);
                accx = fmaf(w2, h2_.x, accx); accy = fmaf(w2, h2_.y, accy);
                accx = fmaf(w3, h3.x, accx);  accy = fmaf(w3, h3.y, accy);
            }
        }
    }
    if (half == 1) {
        pacc[slot][lane] = accx;
        pacc[slot][32 + lane] = accy;
        pden[slot][lane] = denp;
    }
    __syncthreads();
    if (half == 0) {
        accx += pacc[slot][lane];
        accy += pacc[slot][32 + lane];
        float den = denp + pden[slot][lane];
        #pragma unroll
        for (int d = 16; d > 0; d >>= 1) den += __shfl_xor_sync(0xffffffffu, den, d);
        den = fmaxf(den, 1e-12f);
        float vx = -3.0e38f, vy = -3.0e38f;
        if (lane < 24) {
            vx = accx / den + b2[2 * lane];
            vy = (2 * lane + 1 < NC) ? (accy / den + b2[2 * lane + 1]) : -3.0e38f;
        }
        float m = fmaxf(vx, vy);
        #pragma unroll
        for (int d = 16; d > 0; d >>= 1) m = fmaxf(m, __shfl_xor_sync(0xffffffffu, m, d));
        float s = 0.f;
        if (lane < 24) {
            s = __expf(vx - m);
            if (2 * lane + 1 < NC) s += __expf(vy - m);
        }
        #pragma unroll
        for (int d = 16; d > 0; d >>= 1) s += __shfl_xor_sync(0xffffffffu, s, d);
        float ls = logf(s);
        if (lane < 24) {
            out[(size_t)i * NC + 2 * lane] = vx - m - ls;
            if (2 * lane + 1 < NC) out[(size_t)i * NC + 2 * lane + 1] = vy - m - ls;
        }
    }
}

// ---------------- launch ----------------
extern "C" void kernel_launch(void* const* d_in, const int* in_sizes, int n_in,
                              void* d_out, int out_size) {
    const float* x    = (const float*)d_in[0];
    const int*   esrc = (const int*)  d_in[1];
    const int*   edst = (const int*)  d_in[2];
    const float* W1   = (const float*)d_in[3];
    const float* Wl1  = (const float*)d_in[4];
    const float* Wr1  = (const float*)d_in[5];
    const float* b1   = (const float*)d_in[6];
    const float* W2   = (const float*)d_in[7];
    const float* Wl2  = (const float*)d_in[8];
    const float* Wr2  = (const float*)d_in[9];
    const float* b2   = (const float*)d_in[10];
    float* out = (float*)d_out;

    const int smem1 = FIN * S1 * 4;   // 26 KB
    const int smem2 = FIN * S2 * 4;   // 34 KB
    cudaFuncSetAttribute(k_gemm1, cudaFuncAttributeMaxDynamicSharedMemorySize, smem1);
    cudaFuncSetAttribute(k_gemm2, cudaFuncAttributeMaxDynamicSharedMemorySize, smem2);

    int n_scan = Nn + 1;
    int nb = (n_scan + 1023) / 1024;           // 49
    int init_blocks = 2 + (Nn + 1 + 255) / 256;

    // order chosen so launch #4 (the profiled slot) = k_gemm1
    k_init<<<init_blocks, 256>>>(W1, Wl1, Wr1, W2, Wl2, Wr2);
    k_count<<<Ee / 256, 256>>>(esrc);
    k_scan_blocks<<<nb, 1024>>>(n_scan);
    k_gemm1<<<dim3((Nn + 127) / 128, 2), 256, smem1>>>(x);   // #4 <- profiled
    k_finalize_scan<<<nb, 1024>>>(n_scan);
    k_scatter<<<Ee / 256, 256>>>(esrc, edst);
    k_agg1<<<Nn / 4, 256>>>(b1);

    k_gemm2<<<dim3((Nn + 127) / 128, 2), 256, smem2>>>();
    k_agg2<<<Nn / 4, 256>>>(b2, out);
}

// round 8
// speedup vs baseline: 1.1688x; 1.1688x over previous
#include <cuda_runtime.h>
#include <cstdint>

#define Nn 50000
#define Ee 800000
#define FIN 256
#define F1 32
#define H1 8
#define NHID 256
#define NC 47

// ---------------- scratch (device globals: allocation-free) ----------------
__device__ int   g_rowptr[Nn + 1];
__device__ int   g_cursor[Nn];
__device__ int   g_csr_dst[Ee];
__device__ int   g_csr_src[Ee];
__device__ int   g_bsums[64];
__device__ float g_h1[Nn * F1];          // 6.4 MB  (L2 resident)
__device__ float g_el1[Nn * H1];
__device__ float g_er1[Nn * H1];
__device__ float g_w1[Ee * H1];          // 25.6 MB CSR-ordered layer-1 weights
__device__ float g_w2[Ee];               // 3.2 MB  CSR-ordered layer-2 weights
__device__ float g_r1[Nn * NHID];        // 51.2 MB
__device__ float g_h2p[Nn * 48];         // padded h2 (48 cols), 9.6 MB
__device__ float g_el2[Nn];
__device__ float g_er2[Nn];
__device__ float g_B1ext[FIN * 48];      // [W1 | W1@Wl1 | W1@Wr1]
__device__ float g_B2ext[FIN * 50];      // [W2 | 0pad | W2@Wl2 | W2@Wr2]

// ---------------- tf32 mma helpers ----------------
__device__ __forceinline__ uint32_t f2tf32(float f) {
    uint32_t r;
    asm("cvt.rna.tf32.f32 %0, %1;" : "=r"(r) : "f"(f));
    return r;
}

__device__ __forceinline__ void mma_tf32(float* d,
    uint32_t a0, uint32_t a1, uint32_t a2, uint32_t a3,
    uint32_t b0, uint32_t b1) {
    asm volatile(
        "mma.sync.aligned.m16n8k8.row.col.f32.tf32.tf32.f32 "
        "{%0,%1,%2,%3},{%4,%5,%6,%7},{%8,%9},{%0,%1,%2,%3};\n"
        : "+f"(d[0]), "+f"(d[1]), "+f"(d[2]), "+f"(d[3])
        : "r"(a0), "r"(a1), "r"(a2), "r"(a3), "r"(b0), "r"(b1));
}

// ---------------- init: preps + zero counts (fused) ----------------
__global__ void k_init(const float* __restrict__ W1, const float* __restrict__ Wl1,
                       const float* __restrict__ Wr1, const float* __restrict__ W2,
                       const float* __restrict__ Wl2, const float* __restrict__ Wr2) {
    int b = blockIdx.x;
    int k = threadIdx.x;
    if (b == 0) {                       // prep1
        __shared__ float swl[F1 * H1], swr[F1 * H1];
        swl[k] = Wl1[k];
        swr[k] = Wr1[k];
        __syncthreads();
        float row[F1];
        #pragma unroll
        for (int j = 0; j < F1; j++) row[j] = W1[k * F1 + j];
        #pragma unroll
        for (int j = 0; j < F1; j++) g_B1ext[k * 48 + j] = row[j];
        #pragma unroll
        for (int h = 0; h < H1; h++) {
            float sl = 0.f, sr = 0.f;
            #pragma unroll
            for (int j = 0; j < F1; j++) {
                sl = fmaf(row[j], swl[j * H1 + h], sl);
                sr = fmaf(row[j], swr[j * H1 + h], sr);
            }
            g_B1ext[k * 48 + 32 + h] = sl;
            g_B1ext[k * 48 + 40 + h] = sr;
        }
    } else if (b == 1) {                // prep2
        __shared__ float swl2[NC], swr2[NC];
        if (k < NC) { swl2[k] = Wl2[k]; swr2[k] = Wr2[k]; }
        __syncthreads();
        float row[NC];
        #pragma unroll
        for (int j = 0; j < NC; j++) row[j] = W2[k * NC + j];
        #pragma unroll
        for (int j = 0; j < NC; j++) g_B2ext[k * 50 + j] = row[j];
        g_B2ext[k * 50 + 47] = 0.f;
        float sl = 0.f, sr = 0.f;
        #pragma unroll
        for (int j = 0; j < NC; j++) {
            sl = fmaf(row[j], swl2[j], sl);
            sr = fmaf(row[j], swr2[j], sr);
        }
        g_B2ext[k * 50 + 48] = sl;
        g_B2ext[k * 50 + 49] = sr;
    } else {                            // zero rowptr
        int i = (b - 2) * 256 + k;
        if (i < Nn + 1) g_rowptr[i] = 0;
    }
}

// ---------------- CSR build ----------------
__global__ void k_count(const int* __restrict__ src) {
    int e = blockIdx.x * blockDim.x + threadIdx.x;
    if (e < Ee) atomicAdd(&g_rowptr[src[e]], 1);
}

__global__ void k_scan_blocks(int n) {
    __shared__ int wsum[32];
    int tid = threadIdx.x;
    int gid = blockIdx.x * 1024 + tid;
    int v = (gid < n) ? g_rowptr[gid] : 0;
    int lane = tid & 31, wid = tid >> 5;
    int x = v;
    #pragma unroll
    for (int d = 1; d < 32; d <<= 1) {
        int t = __shfl_up_sync(0xffffffffu, x, d);
        if (lane >= d) x += t;
    }
    if (lane == 31) wsum[wid] = x;
    __syncthreads();
    if (wid == 0) {
        int w = wsum[lane];
        #pragma unroll
        for (int d = 1; d < 32; d <<= 1) {
            int t = __shfl_up_sync(0xffffffffu, w, d);
            if (lane >= d) w += t;
        }
        wsum[lane] = w;
    }
    __syncthreads();
    int incl = x + (wid > 0 ? wsum[wid - 1] : 0);
    if (gid < n) g_rowptr[gid] = incl - v;   // exclusive
    if (tid == 1023) g_bsums[blockIdx.x] = incl;
}

__global__ void k_finalize_scan(int n) {
    __shared__ int soff;
    int tid = threadIdx.x;
    if (tid < 32) {
        int v1 = (tid      < (int)blockIdx.x) ? g_bsums[tid]      : 0;
        int v2 = (tid + 32 < (int)blockIdx.x) ? g_bsums[tid + 32] : 0;
        int s = v1 + v2;
        #pragma unroll
        for (int d = 16; d > 0; d >>= 1) s += __shfl_xor_sync(0xffffffffu, s, d);
        if (tid == 0) soff = s;
    }
    __syncthreads();
    int gid = blockIdx.x * 1024 + tid;
    if (gid < n) {
        int v = g_rowptr[gid] + soff;
        g_rowptr[gid] = v;
        if (gid < Nn) g_cursor[gid] = v;
    }
}

// scatter + layer-1 attention weights (edge-parallel, high MLP)
__global__ void k_scatter_w(const int* __restrict__ src, const int* __restrict__ dst) {
    int e = blockIdx.x * blockDim.x + threadIdx.x;
    if (e >= Ee) return;
    int s = src[e], d = dst[e];
    int pos = atomicAdd(&g_cursor[s], 1);
    g_csr_dst[pos] = d;
    g_csr_src[pos] = s;
    const float4* el4 = (const float4*)(g_el1 + (size_t)s * H1);
    const float4* er4 = (const float4*)(g_er1 + (size_t)d * H1);
    float4 la = el4[0], lb = el4[1];
    float4 ra = er4[0], rb = er4[1];
    float el_[H1] = {la.x, la.y, la.z, la.w, lb.x, lb.y, lb.z, lb.w};
    float er_[H1] = {ra.x, ra.y, ra.z, ra.w, rb.x, rb.y, rb.z, rb.w};
    float w[H1];
    #pragma unroll
    for (int h = 0; h < H1; h++) {
        float a = el_[h] + er_[h];
        float lr = a > 0.f ? a : 0.2f * a;
        w[h] = __expf(lr);
    }
    float4* w4 = (float4*)(g_w1 + (size_t)pos * H1);
    w4[0] = make_float4(w[0], w[1], w[2], w[3]);
    w4[1] = make_float4(w[4], w[5], w[6], w[7]);
}

// layer-2 attention weights (edge-parallel, after gemm2)
__global__ void k_weights2() {
    int e = blockIdx.x * blockDim.x + threadIdx.x;
    if (e >= Ee) return;
    float a = g_el2[g_csr_src[e]] + g_er2[g_csr_dst[e]];
    float lr = a > 0.f ? a : 0.2f * a;
    g_w2[e] = __expf(lr);
}

// ---------------- GEMM1 (tf32, 512 thr, in-block N-split) ----------------
// warps 0-7: rows (w&7)*16, n-tiles 0..2; warps 8-15: same rows, n-tiles 3..5.
#define S1 50
__global__ void __launch_bounds__(512, 2) k_gemm1(const float* __restrict__ x) {
    extern __shared__ uint32_t sm1[];
    uint32_t* sB = sm1;                      // [256][S1], 48 cols
    int tx = threadIdx.x, lane = tx & 31, wid = tx >> 5;
    for (int i = tx; i < FIN * 48; i += 512) {
        int k = i / 48, n = i - k * 48;
        sB[k * S1 + n] = f2tf32(g_B1ext[i]);
    }
    __syncthreads();

    int g = lane >> 2, c = lane & 3;
    int wr = wid & 7, ng = wid >> 3;
    int row0 = blockIdx.x * 128 + wr * 16 + g;
    int row1 = row0 + 8;
    bool v0 = row0 < Nn, v1 = row1 < Nn;
    const float4* A0 = (const float4*)(x + (size_t)row0 * FIN);
    const float4* A1 = (const float4*)(x + (size_t)row1 * FIN);
    const float4 z4 = make_float4(0.f, 0.f, 0.f, 0.f);

    float acc[3][4];
    #pragma unroll
    for (int nt = 0; nt < 3; nt++)
        #pragma unroll
        for (int j = 0; j < 4; j++) acc[nt][j] = 0.f;

    float4 b0[4], b1[4];
    #pragma unroll
    for (int t = 0; t < 4; t++) {
        b0[t] = v0 ? A0[t * 4 + c] : z4;
        b1[t] = v1 ? A1[t * 4 + c] : z4;
    }
    #pragma unroll
    for (int ch = 0; ch < 4; ch++) {
        float4 n0[4], n1[4];
        #pragma unroll
        for (int t = 0; t < 4; t++) {
            n0[t] = (v0 && ch < 3) ? A0[(ch + 1) * 16 + t * 4 + c] : z4;
            n1[t] = (v1 && ch < 3) ? A1[(ch + 1) * 16 + t * 4 + c] : z4;
        }
        #pragma unroll
        for (int t = 0; t < 4; t++) {
            int wnd = ch * 4 + t;
            uint32_t a00 = f2tf32(b0[t].x), a01 = f2tf32(b0[t].y), a02 = f2tf32(b0[t].z), a03 = f2tf32(b0[t].w);
            uint32_t a10 = f2tf32(b1[t].x), a11 = f2tf32(b1[t].y), a12 = f2tf32(b1[t].z), a13 = f2tf32(b1[t].w);
            const uint32_t* bA = sB + (wnd * 16 + 4 * c) * S1 + ng * 24;
            #pragma unroll
            for (int nt = 0; nt < 3; nt++)
                mma_tf32(acc[nt], a00, a10, a01, a11, bA[nt * 8 + g], bA[S1 + nt * 8 + g]);
            #pragma unroll
            for (int nt = 0; nt < 3; nt++)
                mma_tf32(acc[nt], a02, a12, a03, a13, bA[2 * S1 + nt * 8 + g], bA[3 * S1 + nt * 8 + g]);
        }
        #pragma unroll
        for (int t = 0; t < 4; t++) { b0[t] = n0[t]; b1[t] = n1[t]; }
    }
    #pragma unroll
    for (int nt = 0; nt < 3; nt++) {
        int ntg = ng * 3 + nt;
        int col = ntg * 8 + 2 * c;
        if (ntg < 4) {
            if (v0) *(float2*)&g_h1[row0 * F1 + col] = make_float2(acc[nt][0], acc[nt][1]);
            if (v1) *(float2*)&g_h1[row1 * F1 + col] = make_float2(acc[nt][2], acc[nt][3]);
        } else if (ntg == 4) {
            if (v0) *(float2*)&g_el1[row0 * H1 + 2 * c] = make_float2(acc[nt][0], acc[nt][1]);
            if (v1) *(float2*)&g_el1[row1 * H1 + 2 * c] = make_float2(acc[nt][2], acc[nt][3]);
        } else {
            if (v0) *(float2*)&g_er1[row0 * H1 + 2 * c] = make_float2(acc[nt][0], acc[nt][1]);
            if (v1) *(float2*)&g_er1[row1 * H1 + 2 * c] = make_float2(acc[nt][2], acc[nt][3]);
        }
    }
}

// ---------------- GEMM2 (tf32, 512 thr, in-block N-split, 8 n-tiles) ----------------
// warps 0-7: tiles 0..3; warps 8-15: tiles 4..7 (cols 50..63 zero-padded).
#define S2 66
__global__ void __launch_bounds__(512, 2) k_gemm2() {
    extern __shared__ uint32_t sm2[];
    uint32_t* sB = sm2;                      // [256][S2], 64 cols
    int tx = threadIdx.x, lane = tx & 31, wid = tx >> 5;
    for (int i = tx; i < FIN * 50; i += 512) {
        int k = i / 50, n = i - k * 50;
        sB[k * S2 + n] = f2tf32(g_B2ext[i]);
    }
    for (int i = tx; i < FIN * 14; i += 512) {
        int k = i / 14, n = 50 + (i - k * 14);
        sB[k * S2 + n] = 0u;
    }
    __syncthreads();

    int g = lane >> 2, c = lane & 3;
    int wr = wid & 7, ng = wid >> 3;
    int row0 = blockIdx.x * 128 + wr * 16 + g;
    int row1 = row0 + 8;
    bool v0 = row0 < Nn, v1 = row1 < Nn;
    const float4* A0 = (const float4*)(g_r1 + (size_t)row0 * FIN);
    const float4* A1 = (const float4*)(g_r1 + (size_t)row1 * FIN);
    const float4 z4 = make_float4(0.f, 0.f, 0.f, 0.f);

    float acc[4][4];
    #pragma unroll
    for (int nt = 0; nt < 4; nt++)
        #pragma unroll
        for (int j = 0; j < 4; j++) acc[nt][j] = 0.f;

    float4 b0[4], b1[4];
    #pragma unroll
    for (int t = 0; t < 4; t++) {
        b0[t] = v0 ? A0[t * 4 + c] : z4;
        b1[t] = v1 ? A1[t * 4 + c] : z4;
    }
    #pragma unroll
    for (int ch = 0; ch < 4; ch++) {
        float4 n0[4], n1[4];
        #pragma unroll
        for (int t = 0; t < 4; t++) {
            n0[t] = (v0 && ch < 3) ? A0[(ch + 1) * 16 + t * 4 + c] : z4;
            n1[t] = (v1 && ch < 3) ? A1[(ch + 1) * 16 + t * 4 + c] : z4;
        }
        #pragma unroll
        for (int t = 0; t < 4; t++) {
            int wnd = ch * 4 + t;
            uint32_t a00 = f2tf32(b0[t].x), a01 = f2tf32(b0[t].y), a02 = f2tf32(b0[t].z), a03 = f2tf32(b0[t].w);
            uint32_t a10 = f2tf32(b1[t].x), a11 = f2tf32(b1[t].y), a12 = f2tf32(b1[t].z), a13 = f2tf32(b1[t].w);
            const uint32_t* bA = sB + (wnd * 16 + 4 * c) * S2 + ng * 32;
            #pragma unroll
            for (int nt = 0; nt < 4; nt++)
                mma_tf32(acc[nt], a00, a10, a01, a11, bA[nt * 8 + g], bA[S2 + nt * 8 + g]);
            #pragma unroll
            for (int nt = 0; nt < 4; nt++)
                mma_tf32(acc[nt], a02, a12, a03, a13, bA[2 * S2 + nt * 8 + g], bA[3 * S2 + nt * 8 + g]);
        }
        #pragma unroll
        for (int t = 0; t < 4; t++) { b0[t] = n0[t]; b1[t] = n1[t]; }
    }
    #pragma unroll
    for (int nt = 0; nt < 4; nt++) {
        int col = (ng * 4 + nt) * 8 + 2 * c;
        if (col < 48) {
            if (v0) *(float2*)&g_h2p[(size_t)row0 * 48 + col] = make_float2(acc[nt][0], acc[nt][1]);
            if (v1) *(float2*)&g_h2p[(size_t)row1 * 48 + col] = make_float2(acc[nt][2], acc[nt][3]);
        } else if (col == 48) {
            if (v0) { g_el2[row0] = acc[nt][0]; g_er2[row0] = acc[nt][1]; }
            if (v1) { g_el2[row1] = acc[nt][2]; g_er2[row1] = acc[nt][3]; }
        }
    }
}

// ---------------- layer-1 aggregation (precomputed weights) ----------------
__global__ void k_agg1(const float* __restrict__ b1) {
    __shared__ float ws[8][32 * 8];    // [warp][edge][head]
    int wid = threadIdx.x >> 5, lane = threadIdx.x & 31;
    int i = blockIdx.x * 8 + wid;

    float acc[H1], denp[H1];
    #pragma unroll
    for (int h = 0; h < H1; h++) { acc[h] = 0.f; denp[h] = 0.f; }

    int beg = g_rowptr[i], end = g_rowptr[i + 1];
    for (int base = beg; base < end; base += 32) {
        int nb = min(32, end - base);
        int dstl = 0;
        float4 wa = make_float4(0.f, 0.f, 0.f, 0.f), wb = wa;
        if (lane < nb) {
            dstl = g_csr_dst[base + lane];
            const float4* w4 = (const float4*)(g_w1 + (size_t)(base + lane) * H1);
            wa = w4[0]; wb = w4[1];
            denp[0] += wa.x; denp[1] += wa.y; denp[2] += wa.z; denp[3] += wa.w;
            denp[4] += wb.x; denp[5] += wb.y; denp[6] += wb.z; denp[7] += wb.w;
        }
        float4* wrow = (float4*)&ws[wid][lane * 8];
        wrow[0] = wa;
        wrow[1] = wb;
        __syncwarp();
        for (int j = 0; j < nb; j += 4) {
            int d0 = __shfl_sync(0xffffffffu, dstl, j);
            int d1 = __shfl_sync(0xffffffffu, dstl, j + 1);
            int d2 = __shfl_sync(0xffffffffu, dstl, j + 2);
            int d3 = __shfl_sync(0xffffffffu, dstl, j + 3);
            float hv0 = g_h1[d0 * F1 + lane];
            float hv1 = g_h1[d1 * F1 + lane];
            float hv2 = g_h1[d2 * F1 + lane];
            float hv3 = g_h1[d3 * F1 + lane];
            const float4* wj = (const float4*)&ws[wid][j * 8];
            #pragma unroll
            for (int u = 0; u < 4; u++) {
                float hv = (u == 0) ? hv0 : (u == 1) ? hv1 : (u == 2) ? hv2 : hv3;
                float4 qa = wj[u * 2], qb = wj[u * 2 + 1];
                acc[0] = fmaf(qa.x, hv, acc[0]);
                acc[1] = fmaf(qa.y, hv, acc[1]);
                acc[2] = fmaf(qa.z, hv, acc[2]);
                acc[3] = fmaf(qa.w, hv, acc[3]);
                acc[4] = fmaf(qb.x, hv, acc[4]);
                acc[5] = fmaf(qb.y, hv, acc[5]);
                acc[6] = fmaf(qb.z, hv, acc[6]);
                acc[7] = fmaf(qb.w, hv, acc[7]);
            }
        }
        __syncwarp();
    }
    float bb = b1[lane];
    #pragma unroll
    for (int h = 0; h < H1; h++) {
        float t = denp[h];
        #pragma unroll
        for (int d = 16; d > 0; d >>= 1) t += __shfl_xor_sync(0xffffffffu, t, d);
        float o = acc[h] / fmaxf(t, 1e-12f) + bb;
        float e = o > 0.f ? o : (__expf(o) - 1.f);   // ELU
        g_r1[(size_t)i * NHID + h * F1 + lane] = e;
    }
}

// ---------------- layer-2 aggregation (precomputed weights) + log_softmax ----------------
__global__ void k_agg2(const float* __restrict__ b2, float* __restrict__ out) {
    int wid = threadIdx.x >> 5, lane = threadIdx.x & 31;
    int i = blockIdx.x * 8 + wid;
    float accx = 0.f, accy = 0.f, denp = 0.f;
    int beg = g_rowptr[i], end = g_rowptr[i + 1];
    for (int base = beg; base < end; base += 32) {
        int nb = min(32, end - base);
        int dstl = 0;
        float wl_ = 0.f;
        if (lane < nb) {
            dstl = g_csr_dst[base + lane];
            wl_ = g_w2[base + lane];
            denp += wl_;
        }
        for (int j = 0; j < nb; j += 4) {
            #pragma unroll
            for (int u = 0; u < 4; u++) {
                int d = __shfl_sync(0xffffffffu, dstl, j + u);
                float wv = __shfl_sync(0xffffffffu, wl_, j + u);
                if (lane < 24) {
                    float2 hv = *(const float2*)&g_h2p[(size_t)d * 48 + 2 * lane];
                    accx = fmaf(wv, hv.x, accx);
                    accy = fmaf(wv, hv.y, accy);
                }
            }
        }
    }
    float den = denp;
    #pragma unroll
    for (int d = 16; d > 0; d >>= 1) den += __shfl_xor_sync(0xffffffffu, den, d);
    den = fmaxf(den, 1e-12f);
    float vx = -3.0e38f, vy = -3.0e38f;
    if (lane < 24) {
        vx = accx / den + b2[2 * lane];
        vy = (2 * lane + 1 < NC) ? (accy / den + b2[2 * lane + 1]) : -3.0e38f;
    }
    float m = fmaxf(vx, vy);
    #pragma unroll
    for (int d = 16; d > 0; d >>= 1) m = fmaxf(m, __shfl_xor_sync(0xffffffffu, m, d));
    float s = 0.f;
    if (lane < 24) {
        s = __expf(vx - m);
        if (2 * lane + 1 < NC) s += __expf(vy - m);
    }
    #pragma unroll
    for (int d = 16; d > 0; d >>= 1) s += __shfl_xor_sync(0xffffffffu, s, d);
    float ls = logf(s);
    if (lane < 24) {
        out[(size_t)i * NC + 2 * lane] = vx - m - ls;
        if (2 * lane + 1 < NC) out[(size_t)i * NC + 2 * lane + 1] = vy - m - ls;
    }
}

// ---------------- launch ----------------
extern "C" void kernel_launch(void* const* d_in, const int* in_sizes, int n_in,
                              void* d_out, int out_size) {
    const float* x    = (const float*)d_in[0];
    const int*   esrc = (const int*)  d_in[1];
    const int*   edst = (const int*)  d_in[2];
    const float* W1   = (const float*)d_in[3];
    const float* Wl1  = (const float*)d_in[4];
    const float* Wr1  = (const float*)d_in[5];
    const float* b1   = (const float*)d_in[6];
    const float* W2   = (const float*)d_in[7];
    const float* Wl2  = (const float*)d_in[8];
    const float* Wr2  = (const float*)d_in[9];
    const float* b2   = (const float*)d_in[10];
    float* out = (float*)d_out;

    const int smem1 = FIN * S1 * 4;   // 51.2 KB
    const int smem2 = FIN * S2 * 4;   // 67.6 KB
    cudaFuncSetAttribute(k_gemm1, cudaFuncAttributeMaxDynamicSharedMemorySize, smem1);
    cudaFuncSetAttribute(k_gemm2, cudaFuncAttributeMaxDynamicSharedMemorySize, smem2);

    int n_scan = Nn + 1;
    int nb = (n_scan + 1023) / 1024;           // 49
    int init_blocks = 2 + (Nn + 1 + 255) / 256;

    // order chosen so launch #4 (the profiled slot) = k_gemm1
    k_init<<<init_blocks, 256>>>(W1, Wl1, Wr1, W2, Wl2, Wr2);
    k_count<<<Ee / 256, 256>>>(esrc);
    k_scan_blocks<<<nb, 1024>>>(n_scan);
    k_gemm1<<<(Nn + 127) / 128, 512, smem1>>>(x);   // #4 <- profiled
    k_finalize_scan<<<nb, 1024>>>(n_scan);
    k_scatter_w<<<Ee / 256, 256>>>(esrc, edst);
    k_agg1<<<Nn / 8, 256>>>(b1);

    k_gemm2<<<(Nn + 127) / 128, 512, smem2>>>();
    k_weights2<<<Ee / 256, 256>>>();
    k_agg2<<<Nn / 8, 256>>>(b2, out);
}

// round 9
// speedup vs baseline: 1.2975x; 1.1101x over previous
#include <cuda_runtime.h>
#include <cstdint>

#define Nn 50000
#define Ee 800000
#define FIN 256
#define F1 32
#define H1 8
#define NHID 256
#define NC 47

// ---------------- scratch (device globals: allocation-free) ----------------
__device__ int   g_rowptr[Nn + 1];
__device__ int   g_cursor[Nn];
__device__ int   g_csr_dst[Ee];
__device__ int   g_bsums[64];
__device__ float g_h1[Nn * F1];          // 6.4 MB  (L2 resident)
__device__ float g_el1[Nn * H1];
__device__ float g_er1[Nn * H1];
__device__ float g_r1[Nn * NHID];        // 51.2 MB
__device__ float g_h2p[Nn * 48];         // padded h2 (48 cols), 9.6 MB
__device__ float g_el2[Nn];
__device__ float g_er2[Nn];
__device__ float g_B1ext[FIN * 48];      // [W1 | W1@Wl1 | W1@Wr1]
__device__ float g_B2ext[FIN * 50];      // [W2 | 0pad | W2@Wl2 | W2@Wr2]

// ---------------- tf32 mma helpers ----------------
__device__ __forceinline__ uint32_t f2tf32(float f) {
    uint32_t r;
    asm("cvt.rna.tf32.f32 %0, %1;" : "=r"(r) : "f"(f));
    return r;
}

__device__ __forceinline__ void mma_tf32(float* d,
    uint32_t a0, uint32_t a1, uint32_t a2, uint32_t a3,
    uint32_t b0, uint32_t b1) {
    asm volatile(
        "mma.sync.aligned.m16n8k8.row.col.f32.tf32.tf32.f32 "
        "{%0,%1,%2,%3},{%4,%5,%6,%7},{%8,%9},{%0,%1,%2,%3};\n"
        : "+f"(d[0]), "+f"(d[1]), "+f"(d[2]), "+f"(d[3])
        : "r"(a0), "r"(a1), "r"(a2), "r"(a3), "r"(b0), "r"(b1));
}

// ---------------- init: preps + zero counts (fused) ----------------
__global__ void k_init(const float* __restrict__ W1, const float* __restrict__ Wl1,
                       const float* __restrict__ Wr1, const float* __restrict__ W2,
                       const float* __restrict__ Wl2, const float* __restrict__ Wr2) {
    int b = blockIdx.x;
    int k = threadIdx.x;
    if (b == 0) {                       // prep1
        __shared__ float swl[F1 * H1], swr[F1 * H1];
        swl[k] = Wl1[k];
        swr[k] = Wr1[k];
        __syncthreads();
        float row[F1];
        #pragma unroll
        for (int j = 0; j < F1; j++) row[j] = W1[k * F1 + j];
        #pragma unroll
        for (int j = 0; j < F1; j++) g_B1ext[k * 48 + j] = row[j];
        #pragma unroll
        for (int h = 0; h < H1; h++) {
            float sl = 0.f, sr = 0.f;
            #pragma unroll
            for (int j = 0; j < F1; j++) {
                sl = fmaf(row[j], swl[j * H1 + h], sl);
                sr = fmaf(row[j], swr[j * H1 + h], sr);
            }
            g_B1ext[k * 48 + 32 + h] = sl;
            g_B1ext[k * 48 + 40 + h] = sr;
        }
    } else if (b == 1) {                // prep2
        __shared__ float swl2[NC], swr2[NC];
        if (k < NC) { swl2[k] = Wl2[k]; swr2[k] = Wr2[k]; }
        __syncthreads();
        float row[NC];
        #pragma unroll
        for (int j = 0; j < NC; j++) row[j] = W2[k * NC + j];
        #pragma unroll
        for (int j = 0; j < NC; j++) g_B2ext[k * 50 + j] = row[j];
        g_B2ext[k * 50 + 47] = 0.f;
        float sl = 0.f, sr = 0.f;
        #pragma unroll
        for (int j = 0; j < NC; j++) {
            sl = fmaf(row[j], swl2[j], sl);
            sr = fmaf(row[j], swr2[j], sr);
        }
        g_B2ext[k * 50 + 48] = sl;
        g_B2ext[k * 50 + 49] = sr;
    } else {                            // zero rowptr
        int i = (b - 2) * 256 + k;
        if (i < Nn + 1) g_rowptr[i] = 0;
    }
}

// ---------------- CSR build ----------------
__global__ void k_count(const int* __restrict__ src) {
    int e = blockIdx.x * blockDim.x + threadIdx.x;
    if (e < Ee) atomicAdd(&g_rowptr[src[e]], 1);
}

__global__ void k_scan_blocks(int n) {
    __shared__ int wsum[32];
    int tid = threadIdx.x;
    int gid = blockIdx.x * 1024 + tid;
    int v = (gid < n) ? g_rowptr[gid] : 0;
    int lane = tid & 31, wid = tid >> 5;
    int x = v;
    #pragma unroll
    for (int d = 1; d < 32; d <<= 1) {
        int t = __shfl_up_sync(0xffffffffu, x, d);
        if (lane >= d) x += t;
    }
    if (lane == 31) wsum[wid] = x;
    __syncthreads();
    if (wid == 0) {
        int w = wsum[lane];
        #pragma unroll
        for (int d = 1; d < 32; d <<= 1) {
            int t = __shfl_up_sync(0xffffffffu, w, d);
            if (lane >= d) w += t;
        }
        wsum[lane] = w;
    }
    __syncthreads();
    int incl = x + (wid > 0 ? wsum[wid - 1] : 0);
    if (gid < n) g_rowptr[gid] = incl - v;   // exclusive
    if (tid == 1023) g_bsums[blockIdx.x] = incl;
}

__global__ void k_finalize_scan(int n) {
    __shared__ int soff;
    int tid = threadIdx.x;
    if (tid < 32) {
        int v1 = (tid      < (int)blockIdx.x) ? g_bsums[tid]      : 0;
        int v2 = (tid + 32 < (int)blockIdx.x) ? g_bsums[tid + 32] : 0;
        int s = v1 + v2;
        #pragma unroll
        for (int d = 16; d > 0; d >>= 1) s += __shfl_xor_sync(0xffffffffu, s, d);
        if (tid == 0) soff = s;
    }
    __syncthreads();
    int gid = blockIdx.x * 1024 + tid;
    if (gid < n) {
        int v = g_rowptr[gid] + soff;
        g_rowptr[gid] = v;
        if (gid < Nn) g_cursor[gid] = v;
    }
}

__global__ void k_scatter(const int* __restrict__ src, const int* __restrict__ dst) {
    int e = blockIdx.x * blockDim.x + threadIdx.x;
    if (e < Ee) {
        int s = src[e];
        int pos = atomicAdd(&g_cursor[s], 1);
        g_csr_dst[pos] = dst[e];
    }
}

// ---------------- GEMM1 (tf32, pair-interleaved B -> LDS.64 operands) ----------------
// 256 thr, 8 warps x 16 rows. B stored as sB[(k>>1)*S1P + 2n + (k&1)]:
// each MMA's (b0,b1) = adjacent k-rows -> one LDS.64. S1P=100 (≡4 mod 16)
// keeps each 16-lane phase bank-bijective: slot = (4c+g+8(nt&1)) mod 16.
#define S1P 100
__global__ void __launch_bounds__(256) k_gemm1(const float* __restrict__ x) {
    extern __shared__ uint32_t sm1[];
    uint32_t* sB = sm1;                      // [128][S1P]
    int tx = threadIdx.x, lane = tx & 31, w = tx >> 5;
    for (int i = tx; i < FIN * 48; i += 256) {
        int k = i / 48, n = i - k * 48;
        sB[(k >> 1) * S1P + 2 * n + (k & 1)] = f2tf32(g_B1ext[i]);
    }
    __syncthreads();

    int g = lane >> 2, c = lane & 3;
    int row0 = blockIdx.x * 128 + w * 16 + g;
    int row1 = row0 + 8;
    bool v0 = row0 < Nn, v1 = row1 < Nn;
    const float4* A0 = (const float4*)(x + (size_t)row0 * FIN);
    const float4* A1 = (const float4*)(x + (size_t)row1 * FIN);
    const float4 z4 = make_float4(0.f, 0.f, 0.f, 0.f);

    float acc[6][4];
    #pragma unroll
    for (int nt = 0; nt < 6; nt++)
        #pragma unroll
        for (int j = 0; j < 4; j++) acc[nt][j] = 0.f;

    float4 b0[4], b1[4];
    #pragma unroll
    for (int t = 0; t < 4; t++) {
        b0[t] = v0 ? A0[t * 4 + c] : z4;
        b1[t] = v1 ? A1[t * 4 + c] : z4;
    }
    #pragma unroll
    for (int ch = 0; ch < 4; ch++) {
        float4 n0[4], n1[4];
        #pragma unroll
        for (int t = 0; t < 4; t++) {
            n0[t] = (v0 && ch < 3) ? A0[(ch + 1) * 16 + t * 4 + c] : z4;
            n1[t] = (v1 && ch < 3) ? A1[(ch + 1) * 16 + t * 4 + c] : z4;
        }
        #pragma unroll
        for (int t = 0; t < 4; t++) {
            int wnd = ch * 4 + t;
            uint32_t a00 = f2tf32(b0[t].x), a01 = f2tf32(b0[t].y), a02 = f2tf32(b0[t].z), a03 = f2tf32(b0[t].w);
            uint32_t a10 = f2tf32(b1[t].x), a11 = f2tf32(b1[t].y), a12 = f2tf32(b1[t].z), a13 = f2tf32(b1[t].w);
            const uint32_t* bP = sB + (wnd * 8 + 2 * c) * S1P + 2 * g;   // rows (4c,4c+1)
            #pragma unroll
            for (int nt = 0; nt < 6; nt++) {
                uint2 bb = *(const uint2*)(bP + 16 * nt);
                mma_tf32(acc[nt], a00, a10, a01, a11, bb.x, bb.y);
            }
            const uint32_t* bQ = bP + S1P;                               // rows (4c+2,4c+3)
            #pragma unroll
            for (int nt = 0; nt < 6; nt++) {
                uint2 bb = *(const uint2*)(bQ + 16 * nt);
                mma_tf32(acc[nt], a02, a12, a03, a13, bb.x, bb.y);
            }
        }
        #pragma unroll
        for (int t = 0; t < 4; t++) { b0[t] = n0[t]; b1[t] = n1[t]; }
    }
    #pragma unroll
    for (int nt = 0; nt < 4; nt++) {
        int col = nt * 8 + 2 * c;
        if (v0) *(float2*)&g_h1[row0 * F1 + col] = make_float2(acc[nt][0], acc[nt][1]);
        if (v1) *(float2*)&g_h1[row1 * F1 + col] = make_float2(acc[nt][2], acc[nt][3]);
    }
    if (v0) *(float2*)&g_el1[row0 * H1 + 2 * c] = make_float2(acc[4][0], acc[4][1]);
    if (v1) *(float2*)&g_el1[row1 * H1 + 2 * c] = make_float2(acc[4][2], acc[4][3]);
    if (v0) *(float2*)&g_er1[row0 * H1 + 2 * c] = make_float2(acc[5][0], acc[5][1]);
    if (v1) *(float2*)&g_er1[row1 * H1 + 2 * c] = make_float2(acc[5][2], acc[5][3]);
}

// ---------------- GEMM2 (tf32, pair-interleaved B, 7 n-tiles) ----------------
// cols 0..46 h2p, 47 pad, 48 el2, 49 er2, 50..55 pad. S2P=116 (≡4 mod 16).
#define S2P 116
__global__ void __launch_bounds__(256) k_gemm2() {
    extern __shared__ uint32_t sm2[];
    uint32_t* sB = sm2;                      // [128][S2P]
    int tx = threadIdx.x, lane = tx & 31, w = tx >> 5;
    for (int i = tx; i < FIN * 50; i += 256) {
        int k = i / 50, n = i - k * 50;
        sB[(k >> 1) * S2P + 2 * n + (k & 1)] = f2tf32(g_B2ext[i]);
    }
    for (int i = tx; i < FIN * 6; i += 256) {
        int k = i / 6, n = 50 + (i - k * 6);
        sB[(k >> 1) * S2P + 2 * n + (k & 1)] = 0u;
    }
    __syncthreads();

    int g = lane >> 2, c = lane & 3;
    int row0 = blockIdx.x * 128 + w * 16 + g;
    int row1 = row0 + 8;
    bool v0 = row0 < Nn, v1 = row1 < Nn;
    const float4* A0 = (const float4*)(g_r1 + (size_t)row0 * FIN);
    const float4* A1 = (const float4*)(g_r1 + (size_t)row1 * FIN);
    const float4 z4 = make_float4(0.f, 0.f, 0.f, 0.f);

    float acc[7][4];
    #pragma unroll
    for (int nt = 0; nt < 7; nt++)
        #pragma unroll
        for (int j = 0; j < 4; j++) acc[nt][j] = 0.f;

    float4 b0[4], b1[4];
    #pragma unroll
    for (int t = 0; t < 4; t++) {
        b0[t] = v0 ? A0[t * 4 + c] : z4;
        b1[t] = v1 ? A1[t * 4 + c] : z4;
    }
    #pragma unroll
    for (int ch = 0; ch < 4; ch++) {
        float4 n0[4], n1[4];
        #pragma unroll
        for (int t = 0; t < 4; t++) {
            n0[t] = (v0 && ch < 3) ? A0[(ch + 1) * 16 + t * 4 + c] : z4;
            n1[t] = (v1 && ch < 3) ? A1[(ch + 1) * 16 + t * 4 + c] : z4;
        }
        #pragma unroll
        for (int t = 0; t < 4; t++) {
            int wnd = ch * 4 + t;
            uint32_t a00 = f2tf32(b0[t].x), a01 = f2tf32(b0[t].y), a02 = f2tf32(b0[t].z), a03 = f2tf32(b0[t].w);
            uint32_t a10 = f2tf32(b1[t].x), a11 = f2tf32(b1[t].y), a12 = f2tf32(b1[t].z), a13 = f2tf32(b1[t].w);
            const uint32_t* bP = sB + (wnd * 8 + 2 * c) * S2P + 2 * g;
            #pragma unroll
            for (int nt = 0; nt < 7; nt++) {
                uint2 bb = *(const uint2*)(bP + 16 * nt);
                mma_tf32(acc[nt], a00, a10, a01, a11, bb.x, bb.y);
            }
            const uint32_t* bQ = bP + S2P;
            #pragma unroll
            for (int nt = 0; nt < 7; nt++) {
                uint2 bb = *(const uint2*)(bQ + 16 * nt);
                mma_tf32(acc[nt], a02, a12, a03, a13, bb.x, bb.y);
            }
        }
        #pragma unroll
        for (int t = 0; t < 4; t++) { b0[t] = n0[t]; b1[t] = n1[t]; }
    }
    #pragma unroll
    for (int nt = 0; nt < 7; nt++) {
        int col = nt * 8 + 2 * c;
        if (col < 48) {
            if (v0) *(float2*)&g_h2p[(size_t)row0 * 48 + col] = make_float2(acc[nt][0], acc[nt][1]);
            if (v1) *(float2*)&g_h2p[(size_t)row1 * 48 + col] = make_float2(acc[nt][2], acc[nt][3]);
        } else if (col == 48) {
            if (v0) { g_el2[row0] = acc[nt][0]; g_er2[row0] = acc[nt][1]; }
            if (v1) { g_el2[row1] = acc[nt][2]; g_er2[row1] = acc[nt][3]; }
        }
    }
}

// ---------------- layer-1 aggregation + bias + ELU -> r1 (R6 version) ----------------
__global__ void k_agg1(const float* __restrict__ b1) {
    __shared__ float ws[8][32 * 8];    // [warp][edge][head]
    int wid = threadIdx.x >> 5, lane = threadIdx.x & 31;
    int i = blockIdx.x * 8 + wid;

    float el_own = (lane < H1) ? g_el1[i * H1 + lane] : 0.f;
    float elh[H1];
    #pragma unroll
    for (int h = 0; h < H1; h++) elh[h] = __shfl_sync(0xffffffffu, el_own, h);

    float acc[H1], denp[H1];
    #pragma unroll
    for (int h = 0; h < H1; h++) { acc[h] = 0.f; denp[h] = 0.f; }

    int beg = g_rowptr[i], end = g_rowptr[i + 1];
    for (int base = beg; base < end; base += 32) {
        int nb = min(32, end - base);
        int dstl = (lane < nb) ? g_csr_dst[base + lane] : 0;
        float w_own[H1];
        if (lane < nb) {
            const float4* er4 = (const float4*)(g_er1 + (size_t)dstl * H1);
            float4 ea = er4[0], eb = er4[1];
            float er_[H1] = {ea.x, ea.y, ea.z, ea.w, eb.x, eb.y, eb.z, eb.w};
            #pragma unroll
            for (int h = 0; h < H1; h++) {
                float a = elh[h] + er_[h];
                float lr = a > 0.f ? a : 0.2f * a;
                float wv = __expf(lr);
                w_own[h] = wv;
                denp[h] += wv;
            }
        } else {
            #pragma unroll
            for (int h = 0; h < H1; h++) w_own[h] = 0.f;
        }
        float4* wrow = (float4*)&ws[wid][lane * 8];
        wrow[0] = make_float4(w_own[0], w_own[1], w_own[2], w_own[3]);
        wrow[1] = make_float4(w_own[4], w_own[5], w_own[6], w_own[7]);
        __syncwarp();
        for (int j = 0; j < nb; j += 4) {
            int d0 = __shfl_sync(0xffffffffu, dstl, j);
            int d1 = __shfl_sync(0xffffffffu, dstl, j + 1);
            int d2 = __shfl_sync(0xffffffffu, dstl, j + 2);
            int d3 = __shfl_sync(0xffffffffu, dstl, j + 3);
            float hv0 = g_h1[d0 * F1 + lane];
            float hv1 = g_h1[d1 * F1 + lane];
            float hv2 = g_h1[d2 * F1 + lane];
            float hv3 = g_h1[d3 * F1 + lane];
            const float4* wj = (const float4*)&ws[wid][j * 8];
            #pragma unroll
            for (int u = 0; u < 4; u++) {
                float hv = (u == 0) ? hv0 : (u == 1) ? hv1 : (u == 2) ? hv2 : hv3;
                float4 wa = wj[u * 2], wb = wj[u * 2 + 1];
                acc[0] = fmaf(wa.x, hv, acc[0]);
                acc[1] = fmaf(wa.y, hv, acc[1]);
                acc[2] = fmaf(wa.z, hv, acc[2]);
                acc[3] = fmaf(wa.w, hv, acc[3]);
                acc[4] = fmaf(wb.x, hv, acc[4]);
                acc[5] = fmaf(wb.y, hv, acc[5]);
                acc[6] = fmaf(wb.z, hv, acc[6]);
                acc[7] = fmaf(wb.w, hv, acc[7]);
            }
        }
        __syncwarp();
    }
    float bb = b1[lane];
    #pragma unroll
    for (int h = 0; h < H1; h++) {
        float t = denp[h];
        #pragma unroll
        for (int d = 16; d > 0; d >>= 1) t += __shfl_xor_sync(0xffffffffu, t, d);
        float o = acc[h] / fmaxf(t, 1e-12f) + bb;
        float e = o > 0.f ? o : (__expf(o) - 1.f);   // ELU
        g_r1[(size_t)i * NHID + h * F1 + lane] = e;
    }
}

// ---------------- layer-2 aggregation + log_softmax (R6 version, h2p float2) ----------------
__global__ void k_agg2(const float* __restrict__ b2, float* __restrict__ out) {
    int wid = threadIdx.x >> 5, lane = threadIdx.x & 31;
    int i = blockIdx.x * 8 + wid;
    float el = g_el2[i];
    float accx = 0.f, accy = 0.f, denp = 0.f;
    int beg = g_rowptr[i], end = g_rowptr[i + 1];
    for (int base = beg; base < end; base += 32) {
        int nb = min(32, end - base);
        int dstl = (lane < nb) ? g_csr_dst[base + lane] : 0;
        float wl_ = 0.f;
        if (lane < nb) {
            float a = el + g_er2[dstl];
            float lr = a > 0.f ? a : 0.2f * a;
            wl_ = __expf(lr);
            denp += wl_;
        }
        for (int j = 0; j < nb; j += 4) {
            #pragma unroll
            for (int u = 0; u < 4; u++) {
                int d = __shfl_sync(0xffffffffu, dstl, j + u);
                float wv = __shfl_sync(0xffffffffu, wl_, j + u);
                if (lane < 24) {
                    float2 hv = *(const float2*)&g_h2p[(size_t)d * 48 + 2 * lane];
                    accx = fmaf(wv, hv.x, accx);
                    accy = fmaf(wv, hv.y, accy);
                }
            }
        }
    }
    float den = denp;
    #pragma unroll
    for (int d = 16; d > 0; d >>= 1) den += __shfl_xor_sync(0xffffffffu, den, d);
    den = fmaxf(den, 1e-12f);
    float vx = -3.0e38f, vy = -3.0e38f;
    if (lane < 24) {
        vx = accx / den + b2[2 * lane];
        vy = (2 * lane + 1 < NC) ? (accy / den + b2[2 * lane + 1]) : -3.0e38f;
    }
    float m = fmaxf(vx, vy);
    #pragma unroll
    for (int d = 16; d > 0; d >>= 1) m = fmaxf(m, __shfl_xor_sync(0xffffffffu, m, d));
    float s = 0.f;
    if (lane < 24) {
        s = __expf(vx - m);
        if (2 * lane + 1 < NC) s += __expf(vy - m);
    }
    #pragma unroll
    for (int d = 16; d > 0; d >>= 1) s += __shfl_xor_sync(0xffffffffu, s, d);
    float ls = logf(s);
    if (lane < 24) {
        out[(size_t)i * NC + 2 * lane] = vx - m - ls;
        if (2 * lane + 1 < NC) out[(size_t)i * NC + 2 * lane + 1] = vy - m - ls;
    }
}

// ---------------- launch ----------------
extern "C" void kernel_launch(void* const* d_in, const int* in_sizes, int n_in,
                              void* d_out, int out_size) {
    const float* x    = (const float*)d_in[0];
    const int*   esrc = (const int*)  d_in[1];
    const int*   edst = (const int*)  d_in[2];
    const float* W1   = (const float*)d_in[3];
    const float* Wl1  = (const float*)d_in[4];
    const float* Wr1  = (const float*)d_in[5];
    const float* b1   = (const float*)d_in[6];
    const float* W2   = (const float*)d_in[7];
    const float* Wl2  = (const float*)d_in[8];
    const float* Wr2  = (const float*)d_in[9];
    const float* b2   = (const float*)d_in[10];
    float* out = (float*)d_out;

    const int smem1 = 128 * S1P * 4;   // 51.2 KB
    const int smem2 = 128 * S2P * 4;   // 59.4 KB
    cudaFuncSetAttribute(k_gemm1, cudaFuncAttributeMaxDynamicSharedMemorySize, smem1);
    cudaFuncSetAttribute(k_gemm2, cudaFuncAttributeMaxDynamicSharedMemorySize, smem2);

    int n_scan = Nn + 1;
    int nb = (n_scan + 1023) / 1024;           // 49
    int init_blocks = 2 + (Nn + 1 + 255) / 256;

    // order chosen so launch #4 (the profiled slot) = k_gemm1
    k_init<<<init_blocks, 256>>>(W1, Wl1, Wr1, W2, Wl2, Wr2);
    k_count<<<Ee / 256, 256>>>(esrc);
    k_scan_blocks<<<nb, 1024>>>(n_scan);
    k_gemm1<<<(Nn + 127) / 128, 256, smem1>>>(x);   // #4 <- profiled
    k_finalize_scan<<<nb, 1024>>>(n_scan);
    k_scatter<<<Ee / 256, 256>>>(esrc, edst);
    k_agg1<<<Nn / 8, 256>>>(b1);

    k_gemm2<<<(Nn + 127) / 128, 256, smem2>>>();
    k_agg2<<<Nn / 8, 256>>>(b2, out);
}

// round 10
// speedup vs baseline: 1.3472x; 1.0383x over previous
#include <cuda_runtime.h>
#include <cuda_fp16.h>
#include <cstdint>

#define Nn 50000
#define Ee 800000
#define FIN 256
#define F1 32
#define H1 8
#define NHID 256
#define NC 47

// ---------------- scratch (device globals: allocation-free) ----------------
__device__ int    g_rowptr[Nn + 1];
__device__ int    g_cursor[Nn];
__device__ int    g_csr_dst[Ee];
__device__ int    g_bsums[64];
__device__ __half g_h1h[Nn * F1];        // 3.2 MB fp16 gather array (layer 1)
__device__ float  g_el1[Nn * H1];
__device__ __half g_er1h[Nn * H1];       // 0.8 MB fp16 gather array
__device__ float  g_r1[Nn * NHID];       // 51.2 MB
__device__ __half g_h2ph[Nn * 48];       // 4.8 MB fp16 gather array (layer 2)
__device__ float  g_el2[Nn];
__device__ float  g_er2[Nn];
__device__ float  g_B1ext[FIN * 48];     // [W1 | W1@Wl1 | W1@Wr1]
__device__ float  g_B2ext[FIN * 50];     // [W2 | 0pad | W2@Wl2 | W2@Wr2]

// ---------------- tf32 mma helpers ----------------
__device__ __forceinline__ uint32_t f2tf32(float f) {
    uint32_t r;
    asm("cvt.rna.tf32.f32 %0, %1;" : "=r"(r) : "f"(f));
    return r;
}

__device__ __forceinline__ void mma_tf32(float* d,
    uint32_t a0, uint32_t a1, uint32_t a2, uint32_t a3,
    uint32_t b0, uint32_t b1) {
    asm volatile(
        "mma.sync.aligned.m16n8k8.row.col.f32.tf32.tf32.f32 "
        "{%0,%1,%2,%3},{%4,%5,%6,%7},{%8,%9},{%0,%1,%2,%3};\n"
        : "+f"(d[0]), "+f"(d[1]), "+f"(d[2]), "+f"(d[3])
        : "r"(a0), "r"(a1), "r"(a2), "r"(a3), "r"(b0), "r"(b1));
}

// ---------------- init: preps + zero counts (fused) ----------------
__global__ void k_init(const float* __restrict__ W1, const float* __restrict__ Wl1,
                       const float* __restrict__ Wr1, const float* __restrict__ W2,
                       const float* __restrict__ Wl2, const float* __restrict__ Wr2) {
    int b = blockIdx.x;
    int k = threadIdx.x;
    if (b == 0) {                       // prep1
        __shared__ float swl[F1 * H1], swr[F1 * H1];
        swl[k] = Wl1[k];
        swr[k] = Wr1[k];
        __syncthreads();
        float row[F1];
        #pragma unroll
        for (int j = 0; j < F1; j++) row[j] = W1[k * F1 + j];
        #pragma unroll
        for (int j = 0; j < F1; j++) g_B1ext[k * 48 + j] = row[j];
        #pragma unroll
        for (int h = 0; h < H1; h++) {
            float sl = 0.f, sr = 0.f;
            #pragma unroll
            for (int j = 0; j < F1; j++) {
                sl = fmaf(row[j], swl[j * H1 + h], sl);
                sr = fmaf(row[j], swr[j * H1 + h], sr);
            }
            g_B1ext[k * 48 + 32 + h] = sl;
            g_B1ext[k * 48 + 40 + h] = sr;
        }
    } else if (b == 1) {                // prep2
        __shared__ float swl2[NC], swr2[NC];
        if (k < NC) { swl2[k] = Wl2[k]; swr2[k] = Wr2[k]; }
        __syncthreads();
        float row[NC];
        #pragma unroll
        for (int j = 0; j < NC; j++) row[j] = W2[k * NC + j];
        #pragma unroll
        for (int j = 0; j < NC; j++) g_B2ext[k * 50 + j] = row[j];
        g_B2ext[k * 50 + 47] = 0.f;
        float sl = 0.f, sr = 0.f;
        #pragma unroll
        for (int j = 0; j < NC; j++) {
            sl = fmaf(row[j], swl2[j], sl);
            sr = fmaf(row[j], swr2[j], sr);
        }
        g_B2ext[k * 50 + 48] = sl;
        g_B2ext[k * 50 + 49] = sr;
    } else {                            // zero rowptr
        int i = (b - 2) * 256 + k;
        if (i < Nn + 1) g_rowptr[i] = 0;
    }
}

// ---------------- CSR build ----------------
__global__ void k_count(const int* __restrict__ src) {
    int e = blockIdx.x * blockDim.x + threadIdx.x;
    if (e < Ee) atomicAdd(&g_rowptr[src[e]], 1);
}

__global__ void k_scan_blocks(int n) {
    __shared__ int wsum[32];
    int tid = threadIdx.x;
    int gid = blockIdx.x * 1024 + tid;
    int v = (gid < n) ? g_rowptr[gid] : 0;
    int lane = tid & 31, wid = tid >> 5;
    int x = v;
    #pragma unroll
    for (int d = 1; d < 32; d <<= 1) {
        int t = __shfl_up_sync(0xffffffffu, x, d);
        if (lane >= d) x += t;
    }
    if (lane == 31) wsum[wid] = x;
    __syncthreads();
    if (wid == 0) {
        int w = wsum[lane];
        #pragma unroll
        for (int d = 1; d < 32; d <<= 1) {
            int t = __shfl_up_sync(0xffffffffu, w, d);
            if (lane >= d) w += t;
        }
        wsum[lane] = w;
    }
    __syncthreads();
    int incl = x + (wid > 0 ? wsum[wid - 1] : 0);
    if (gid < n) g_rowptr[gid] = incl - v;   // exclusive
    if (tid == 1023) g_bsums[blockIdx.x] = incl;
}

__global__ void k_finalize_scan(int n) {
    __shared__ int soff;
    int tid = threadIdx.x;
    if (tid < 32) {
        int v1 = (tid      < (int)blockIdx.x) ? g_bsums[tid]      : 0;
        int v2 = (tid + 32 < (int)blockIdx.x) ? g_bsums[tid + 32] : 0;
        int s = v1 + v2;
        #pragma unroll
        for (int d = 16; d > 0; d >>= 1) s += __shfl_xor_sync(0xffffffffu, s, d);
        if (tid == 0) soff = s;
    }
    __syncthreads();
    int gid = blockIdx.x * 1024 + tid;
    if (gid < n) {
        int v = g_rowptr[gid] + soff;
        g_rowptr[gid] = v;
        if (gid < Nn) g_cursor[gid] = v;
    }
}

__global__ void k_scatter(const int* __restrict__ src, const int* __restrict__ dst) {
    int e = blockIdx.x * blockDim.x + threadIdx.x;
    if (e < Ee) {
        int s = src[e];
        int pos = atomicAdd(&g_cursor[s], 1);
        g_csr_dst[pos] = dst[e];
    }
}

// ---------------- GEMM1 (tf32, pair-interleaved B, fp16 h1/er1 epilogue) ----------------
#define S1P 100
__global__ void __launch_bounds__(256) k_gemm1(const float* __restrict__ x) {
    extern __shared__ uint32_t sm1[];
    uint32_t* sB = sm1;                      // [128][S1P]
    int tx = threadIdx.x, lane = tx & 31, w = tx >> 5;
    for (int i = tx; i < FIN * 48; i += 256) {
        int k = i / 48, n = i - k * 48;
        sB[(k >> 1) * S1P + 2 * n + (k & 1)] = f2tf32(g_B1ext[i]);
    }
    __syncthreads();

    int g = lane >> 2, c = lane & 3;
    int row0 = blockIdx.x * 128 + w * 16 + g;
    int row1 = row0 + 8;
    bool v0 = row0 < Nn, v1 = row1 < Nn;
    const float4* A0 = (const float4*)(x + (size_t)row0 * FIN);
    const float4* A1 = (const float4*)(x + (size_t)row1 * FIN);
    const float4 z4 = make_float4(0.f, 0.f, 0.f, 0.f);

    float acc[6][4];
    #pragma unroll
    for (int nt = 0; nt < 6; nt++)
        #pragma unroll
        for (int j = 0; j < 4; j++) acc[nt][j] = 0.f;

    float4 b0[4], b1[4];
    #pragma unroll
    for (int t = 0; t < 4; t++) {
        b0[t] = v0 ? A0[t * 4 + c] : z4;
        b1[t] = v1 ? A1[t * 4 + c] : z4;
    }
    #pragma unroll
    for (int ch = 0; ch < 4; ch++) {
        float4 n0[4], n1[4];
        #pragma unroll
        for (int t = 0; t < 4; t++) {
            n0[t] = (v0 && ch < 3) ? A0[(ch + 1) * 16 + t * 4 + c] : z4;
            n1[t] = (v1 && ch < 3) ? A1[(ch + 1) * 16 + t * 4 + c] : z4;
        }
        #pragma unroll
        for (int t = 0; t < 4; t++) {
            int wnd = ch * 4 + t;
            uint32_t a00 = f2tf32(b0[t].x), a01 = f2tf32(b0[t].y), a02 = f2tf32(b0[t].z), a03 = f2tf32(b0[t].w);
            uint32_t a10 = f2tf32(b1[t].x), a11 = f2tf32(b1[t].y), a12 = f2tf32(b1[t].z), a13 = f2tf32(b1[t].w);
            const uint32_t* bP = sB + (wnd * 8 + 2 * c) * S1P + 2 * g;
            #pragma unroll
            for (int nt = 0; nt < 6; nt++) {
                uint2 bb = *(const uint2*)(bP + 16 * nt);
                mma_tf32(acc[nt], a00, a10, a01, a11, bb.x, bb.y);
            }
            const uint32_t* bQ = bP + S1P;
            #pragma unroll
            for (int nt = 0; nt < 6; nt++) {
                uint2 bb = *(const uint2*)(bQ + 16 * nt);
                mma_tf32(acc[nt], a02, a12, a03, a13, bb.x, bb.y);
            }
        }
        #pragma unroll
        for (int t = 0; t < 4; t++) { b0[t] = n0[t]; b1[t] = n1[t]; }
    }
    // h1 as fp16 half2: col = nt*8 + 2c -> half2 index row*16 + nt*4 + c
    #pragma unroll
    for (int nt = 0; nt < 4; nt++) {
        if (v0) ((__half2*)g_h1h)[(size_t)row0 * 16 + nt * 4 + c] = __floats2half2_rn(acc[nt][0], acc[nt][1]);
        if (v1) ((__half2*)g_h1h)[(size_t)row1 * 16 + nt * 4 + c] = __floats2half2_rn(acc[nt][2], acc[nt][3]);
    }
    if (v0) *(float2*)&g_el1[row0 * H1 + 2 * c] = make_float2(acc[4][0], acc[4][1]);
    if (v1) *(float2*)&g_el1[row1 * H1 + 2 * c] = make_float2(acc[4][2], acc[4][3]);
    if (v0) ((__half2*)g_er1h)[(size_t)row0 * 4 + c] = __floats2half2_rn(acc[5][0], acc[5][1]);
    if (v1) ((__half2*)g_er1h)[(size_t)row1 * 4 + c] = __floats2half2_rn(acc[5][2], acc[5][3]);
}

// ---------------- GEMM2 (tf32, pair-interleaved B, fp16 h2p epilogue) ----------------
#define S2P 116
__global__ void __launch_bounds__(256) k_gemm2() {
    extern __shared__ uint32_t sm2[];
    uint32_t* sB = sm2;                      // [128][S2P]
    int tx = threadIdx.x, lane = tx & 31, w = tx >> 5;
    for (int i = tx; i < FIN * 50; i += 256) {
        int k = i / 50, n = i - k * 50;
        sB[(k >> 1) * S2P + 2 * n + (k & 1)] = f2tf32(g_B2ext[i]);
    }
    for (int i = tx; i < FIN * 6; i += 256) {
        int k = i / 6, n = 50 + (i - k * 6);
        sB[(k >> 1) * S2P + 2 * n + (k & 1)] = 0u;
    }
    __syncthreads();

    int g = lane >> 2, c = lane & 3;
    int row0 = blockIdx.x * 128 + w * 16 + g;
    int row1 = row0 + 8;
    bool v0 = row0 < Nn, v1 = row1 < Nn;
    const float4* A0 = (const float4*)(g_r1 + (size_t)row0 * FIN);
    const float4* A1 = (const float4*)(g_r1 + (size_t)row1 * FIN);
    const float4 z4 = make_float4(0.f, 0.f, 0.f, 0.f);

    float acc[7][4];
    #pragma unroll
    for (int nt = 0; nt < 7; nt++)
        #pragma unroll
        for (int j = 0; j < 4; j++) acc[nt][j] = 0.f;

    float4 b0[4], b1[4];
    #pragma unroll
    for (int t = 0; t < 4; t++) {
        b0[t] = v0 ? A0[t * 4 + c] : z4;
        b1[t] = v1 ? A1[t * 4 + c] : z4;
    }
    #pragma unroll
    for (int ch = 0; ch < 4; ch++) {
        float4 n0[4], n1[4];
        #pragma unroll
        for (int t = 0; t < 4; t++) {
            n0[t] = (v0 && ch < 3) ? A0[(ch + 1) * 16 + t * 4 + c] : z4;
            n1[t] = (v1 && ch < 3) ? A1[(ch + 1) * 16 + t * 4 + c] : z4;
        }
        #pragma unroll
        for (int t = 0; t < 4; t++) {
            int wnd = ch * 4 + t;
            uint32_t a00 = f2tf32(b0[t].x), a01 = f2tf32(b0[t].y), a02 = f2tf32(b0[t].z), a03 = f2tf32(b0[t].w);
            uint32_t a10 = f2tf32(b1[t].x), a11 = f2tf32(b1[t].y), a12 = f2tf32(b1[t].z), a13 = f2tf32(b1[t].w);
            const uint32_t* bP = sB + (wnd * 8 + 2 * c) * S2P + 2 * g;
            #pragma unroll
            for (int nt = 0; nt < 7; nt++) {
                uint2 bb = *(const uint2*)(bP + 16 * nt);
                mma_tf32(acc[nt], a00, a10, a01, a11, bb.x, bb.y);
            }
            const uint32_t* bQ = bP + S2P;
            #pragma unroll
            for (int nt = 0; nt < 7; nt++) {
                uint2 bb = *(const uint2*)(bQ + 16 * nt);
                mma_tf32(acc[nt], a02, a12, a03, a13, bb.x, bb.y);
            }
        }
        #pragma unroll
        for (int t = 0; t < 4; t++) { b0[t] = n0[t]; b1[t] = n1[t]; }
    }
    #pragma unroll
    for (int nt = 0; nt < 7; nt++) {
        int col = nt * 8 + 2 * c;
        if (col < 48) {
            if (v0) ((__half2*)g_h2ph)[(size_t)row0 * 24 + nt * 4 + c] = __floats2half2_rn(acc[nt][0], acc[nt][1]);
            if (v1) ((__half2*)g_h2ph)[(size_t)row1 * 24 + nt * 4 + c] = __floats2half2_rn(acc[nt][2], acc[nt][3]);
        } else if (col == 48) {
            if (v0) { g_el2[row0] = acc[nt][0]; g_er2[row0] = acc[nt][1]; }
            if (v1) { g_el2[row1] = acc[nt][2]; g_er2[row1] = acc[nt][3]; }
        }
    }
}

// ---------------- layer-1 aggregation (fp16 gathers, x8 unroll) ----------------
__global__ void k_agg1(const float* __restrict__ b1) {
    __shared__ float ws[8][32 * 8];    // [warp][edge][head]
    int wid = threadIdx.x >> 5, lane = threadIdx.x & 31;
    int i = blockIdx.x * 8 + wid;

    float el_own = (lane < H1) ? g_el1[i * H1 + lane] : 0.f;
    float elh[H1];
    #pragma unroll
    for (int h = 0; h < H1; h++) elh[h] = __shfl_sync(0xffffffffu, el_own, h);

    float acc[H1], denp[H1];
    #pragma unroll
    for (int h = 0; h < H1; h++) { acc[h] = 0.f; denp[h] = 0.f; }

    int beg = g_rowptr[i], end = g_rowptr[i + 1];
    for (int base = beg; base < end; base += 32) {
        int nb = min(32, end - base);
        int dstl = (lane < nb) ? g_csr_dst[base + lane] : 0;
        float w_own[H1];
        if (lane < nb) {
            // er row: 8 halves = 16B, one uint4 load
            uint2 rva = *(const uint2*)(g_er1h + (size_t)dstl * H1);
            uint2 rvb = *(const uint2*)(g_er1h + (size_t)dstl * H1 + 4);
            __half2 e0 = *(__half2*)&rva.x, e1 = *(__half2*)&rva.y;
            __half2 e2 = *(__half2*)&rvb.x, e3 = *(__half2*)&rvb.y;
            float er_[H1] = {__low2float(e0), __high2float(e0), __low2float(e1), __high2float(e1),
                             __low2float(e2), __high2float(e2), __low2float(e3), __high2float(e3)};
            #pragma unroll
            for (int h = 0; h < H1; h++) {
                float a = elh[h] + er_[h];
                float lr = a > 0.f ? a : 0.2f * a;
                float wv = __expf(lr);
                w_own[h] = wv;
                denp[h] += wv;
            }
        } else {
            #pragma unroll
            for (int h = 0; h < H1; h++) w_own[h] = 0.f;
        }
        float4* wrow = (float4*)&ws[wid][lane * 8];
        wrow[0] = make_float4(w_own[0], w_own[1], w_own[2], w_own[3]);
        wrow[1] = make_float4(w_own[4], w_own[5], w_own[6], w_own[7]);
        __syncwarp();
        // x8 unroll: 8 independent 2B gathers in flight (tail lanes w=0, dst=0)
        for (int j = 0; j < nb; j += 8) {
            int dd[8];
            #pragma unroll
            for (int u = 0; u < 8; u++) dd[u] = __shfl_sync(0xffffffffu, dstl, j + u);
            float hv[8];
            #pragma unroll
            for (int u = 0; u < 8; u++) hv[u] = __half2float(g_h1h[(size_t)dd[u] * F1 + lane]);
            const float4* wj = (const float4*)&ws[wid][j * 8];
            #pragma unroll
            for (int u = 0; u < 8; u++) {
                float4 wa = wj[u * 2], wb = wj[u * 2 + 1];
                acc[0] = fmaf(wa.x, hv[u], acc[0]);
                acc[1] = fmaf(wa.y, hv[u], acc[1]);
                acc[2] = fmaf(wa.z, hv[u], acc[2]);
                acc[3] = fmaf(wa.w, hv[u], acc[3]);
                acc[4] = fmaf(wb.x, hv[u], acc[4]);
                acc[5] = fmaf(wb.y, hv[u], acc[5]);
                acc[6] = fmaf(wb.z, hv[u], acc[6]);
                acc[7] = fmaf(wb.w, hv[u], acc[7]);
            }
        }
        __syncwarp();
    }
    float bb = b1[lane];
    #pragma unroll
    for (int h = 0; h < H1; h++) {
        float t = denp[h];
        #pragma unroll
        for (int d = 16; d > 0; d >>= 1) t += __shfl_xor_sync(0xffffffffu, t, d);
        float o = acc[h] / fmaxf(t, 1e-12f) + bb;
        float e = o > 0.f ? o : (__expf(o) - 1.f);   // ELU
        g_r1[(size_t)i * NHID + h * F1 + lane] = e;
    }
}

// ---------------- layer-2 aggregation (fp16 gathers, x8 unroll) + log_softmax ----------------
__global__ void k_agg2(const float* __restrict__ b2, float* __restrict__ out) {
    int wid = threadIdx.x >> 5, lane = threadIdx.x & 31;
    int i = blockIdx.x * 8 + wid;
    float el = g_el2[i];
    float accx = 0.f, accy = 0.f, denp = 0.f;
    int beg = g_rowptr[i], end = g_rowptr[i + 1];
    for (int base = beg; base < end; base += 32) {
        int nb = min(32, end - base);
        int dstl = (lane < nb) ? g_csr_dst[base + lane] : 0;
        float wl_ = 0.f;
        if (lane < nb) {
            float a = el + g_er2[dstl];
            float lr = a > 0.f ? a : 0.2f * a;
            wl_ = __expf(lr);
            denp += wl_;
        }
        for (int j = 0; j < nb; j += 8) {
            int dd[8];
            float wv[8];
            #pragma unroll
            for (int u = 0; u < 8; u++) {
                dd[u] = __shfl_sync(0xffffffffu, dstl, j + u);
                wv[u] = __shfl_sync(0xffffffffu, wl_, j + u);
            }
            if (lane < 24) {
                __half2 hh[8];
                #pragma unroll
                for (int u = 0; u < 8; u++)
                    hh[u] = ((const __half2*)g_h2ph)[(size_t)dd[u] * 24 + lane];
                #pragma unroll
                for (int u = 0; u < 8; u++) {
                    accx = fmaf(wv[u], __low2float(hh[u]), accx);
                    accy = fmaf(wv[u], __high2float(hh[u]), accy);
                }
            }
        }
    }
    float den = denp;
    #pragma unroll
    for (int d = 16; d > 0; d >>= 1) den += __shfl_xor_sync(0xffffffffu, den, d);
    den = fmaxf(den, 1e-12f);
    float vx = -3.0e38f, vy = -3.0e38f;
    if (lane < 24) {
        vx = accx / den + b2[2 * lane];
        vy = (2 * lane + 1 < NC) ? (accy / den + b2[2 * lane + 1]) : -3.0e38f;
    }
    float m = fmaxf(vx, vy);
    #pragma unroll
    for (int d = 16; d > 0; d >>= 1) m = fmaxf(m, __shfl_xor_sync(0xffffffffu, m, d));
    float s = 0.f;
    if (lane < 24) {
        s = __expf(vx - m);
        if (2 * lane + 1 < NC) s += __expf(vy - m);
    }
    #pragma unroll
    for (int d = 16; d > 0; d >>= 1) s += __shfl_xor_sync(0xffffffffu, s, d);
    float ls = logf(s);
    if (lane < 24) {
        out[(size_t)i * NC + 2 * lane] = vx - m - ls;
        if (2 * lane + 1 < NC) out[(size_t)i * NC + 2 * lane + 1] = vy - m - ls;
    }
}

// ---------------- launch ----------------
extern "C" void kernel_launch(void* const* d_in, const int* in_sizes, int n_in,
                              void* d_out, int out_size) {
    const float* x    = (const float*)d_in[0];
    const int*   esrc = (const int*)  d_in[1];
    const int*   edst = (const int*)  d_in[2];
    const float* W1   = (const float*)d_in[3];
    const float* Wl1  = (const float*)d_in[4];
    const float* Wr1  = (const float*)d_in[5];
    const float* b1   = (const float*)d_in[6];
    const float* W2   = (const float*)d_in[7];
    const float* Wl2  = (const float*)d_in[8];
    const float* Wr2  = (const float*)d_in[9];
    const float* b2   = (const float*)d_in[10];
    float* out = (float*)d_out;

    const int smem1 = 128 * S1P * 4;   // 51.2 KB
    const int smem2 = 128 * S2P * 4;   // 59.4 KB
    cudaFuncSetAttribute(k_gemm1, cudaFuncAttributeMaxDynamicSharedMemorySize, smem1);
    cudaFuncSetAttribute(k_gemm2, cudaFuncAttributeMaxDynamicSharedMemorySize, smem2);

    int n_scan = Nn + 1;
    int nb = (n_scan + 1023) / 1024;           // 49
    int init_blocks = 2 + (Nn + 1 + 255) / 256;

    // order chosen so launch #4 (the profiled slot) = k_gemm1
    k_init<<<init_blocks, 256>>>(W1, Wl1, Wr1, W2, Wl2, Wr2);
    k_count<<<Ee / 256, 256>>>(esrc);
    k_scan_blocks<<<nb, 1024>>>(n_scan);
    k_gemm1<<<(Nn + 127) / 128, 256, smem1>>>(x);   // #4 <- profiled
    k_finalize_scan<<<nb, 1024>>>(n_scan);
    k_scatter<<<Ee / 256, 256>>>(esrc, edst);
    k_agg1<<<Nn / 8, 256>>>(b1);

    k_gemm2<<<(Nn + 127) / 128, 256, smem2>>>();
    k_agg2<<<Nn / 8, 256>>>(b2, out);
}

// round 11
// speedup vs baseline: 1.4221x; 1.0556x over previous
#include <cuda_runtime.h>
#include <cuda_fp16.h>
#include <cstdint>

#define Nn 50000
#define Ee 800000
#define FIN 256
#define F1 32
#define H1 8
#define NHID 256
#define NC 47

// ---------------- scratch (device globals: allocation-free) ----------------
__device__ int    g_rowptr[Nn + 1];
__device__ int    g_cursor[Nn];
__device__ int    g_csr_dst[Ee];
__device__ int    g_bsums[64];
__device__ int    g_sflag[64];
__device__ __half g_h1h[Nn * F1];        // 3.2 MB fp16 gather array (layer 1)
__device__ float  g_el1[Nn * H1];
__device__ __half g_er1h[Nn * H1];       // 0.8 MB fp16 gather array
__device__ __half g_r1h[Nn * NHID];      // 25.6 MB fp16 hidden activations
__device__ __half g_h2ph[Nn * 48];       // 4.8 MB fp16 gather array (layer 2)
__device__ float  g_el2[Nn];
__device__ float  g_er2[Nn];

// ---------------- tf32 mma helpers ----------------
__device__ __forceinline__ uint32_t f2tf32(float f) {
    uint32_t r;
    asm("cvt.rna.tf32.f32 %0, %1;" : "=r"(r) : "f"(f));
    return r;
}

__device__ __forceinline__ void mma_tf32(float* d,
    uint32_t a0, uint32_t a1, uint32_t a2, uint32_t a3,
    uint32_t b0, uint32_t b1) {
    asm volatile(
        "mma.sync.aligned.m16n8k8.row.col.f32.tf32.tf32.f32 "
        "{%0,%1,%2,%3},{%4,%5,%6,%7},{%8,%9},{%0,%1,%2,%3};\n"
        : "+f"(d[0]), "+f"(d[1]), "+f"(d[2]), "+f"(d[3])
        : "r"(a0), "r"(a1), "r"(a2), "r"(a3), "r"(b0), "r"(b1));
}

__device__ __forceinline__ float4 h4_to_f4(uint2 r) {
    __half2 p0 = *(__half2*)&r.x, p1 = *(__half2*)&r.y;
    return make_float4(__low2float(p0), __high2float(p0),
                       __low2float(p1), __high2float(p1));
}

// ---------------- zero / sentinel init ----------------
__global__ void k_zero() {
    int i = blockIdx.x * 256 + threadIdx.x;
    if (i < Nn + 1) g_rowptr[i] = 0;
    if (i < 64) { g_bsums[i] = -1; g_sflag[i] = 0; }
}

// ---------------- GEMM1 (tf32, fused: edge count + B prep + MMA) ----------------
// h1 = x@W1 (fp16 out), el1 = x@(W1@Wl1), er1 = x@(W1@Wr1) (cols 32..47)
#define S1P 100
__global__ void __launch_bounds__(256) k_gemm1(const float* __restrict__ x,
                                               const float* __restrict__ W1,
                                               const float* __restrict__ Wl1,
                                               const float* __restrict__ Wr1,
                                               const int* __restrict__ esrc) {
    extern __shared__ uint32_t sm1[];
    uint32_t* sB = sm1;                      // [128][S1P] pair-interleaved
    __shared__ float swl[F1 * H1], swr[F1 * H1];
    int tx = threadIdx.x, lane = tx & 31, w = tx >> 5;

    // edge histogram (grid-stride, independent of smem work)
    for (int e = blockIdx.x * 256 + tx; e < Ee; e += gridDim.x * 256)
        atomicAdd(&g_rowptr[esrc[e]], 1);

    // load W1 into pair-interleaved cols 0..31
    for (int i = tx; i < FIN * F1; i += 256) {
        int k = i >> 5, n = i & 31;
        sB[(k >> 1) * S1P + 2 * n + (k & 1)] = f2tf32(W1[i]);
    }
    swl[tx] = Wl1[tx];
    swr[tx] = Wr1[tx];
    __syncthreads();

    // prep cols 32..47: B[k][32+h] = sum_j W1[k][j]*Wl1[j][h] (and Wr)
    {
        int k = tx;
        float sl[H1], sr[H1];
        #pragma unroll
        for (int h = 0; h < H1; h++) { sl[h] = 0.f; sr[h] = 0.f; }
        #pragma unroll 8
        for (int j = 0; j < F1; j++) {
            float v = __uint_as_float(sB[(k >> 1) * S1P + 2 * j + (k & 1)]);
            #pragma unroll
            for (int h = 0; h < H1; h++) {
                sl[h] = fmaf(v, swl[j * H1 + h], sl[h]);
                sr[h] = fmaf(v, swr[j * H1 + h], sr[h]);
            }
        }
        #pragma unroll
        for (int h = 0; h < H1; h++) {
            sB[(k >> 1) * S1P + 2 * (32 + h) + (k & 1)] = f2tf32(sl[h]);
            sB[(k >> 1) * S1P + 2 * (40 + h) + (k & 1)] = f2tf32(sr[h]);
        }
    }
    __syncthreads();

    int g = lane >> 2, c = lane & 3;
    int row0 = blockIdx.x * 128 + w * 16 + g;
    int row1 = row0 + 8;
    bool v0 = row0 < Nn, v1 = row1 < Nn;
    const float4* A0 = (const float4*)(x + (size_t)row0 * FIN);
    const float4* A1 = (const float4*)(x + (size_t)row1 * FIN);
    const float4 z4 = make_float4(0.f, 0.f, 0.f, 0.f);

    float acc[6][4];
    #pragma unroll
    for (int nt = 0; nt < 6; nt++)
        #pragma unroll
        for (int j = 0; j < 4; j++) acc[nt][j] = 0.f;

    float4 b0[4], b1[4];
    #pragma unroll
    for (int t = 0; t < 4; t++) {
        b0[t] = v0 ? A0[t * 4 + c] : z4;
        b1[t] = v1 ? A1[t * 4 + c] : z4;
    }
    #pragma unroll
    for (int ch = 0; ch < 4; ch++) {
        float4 n0[4], n1[4];
        #pragma unroll
        for (int t = 0; t < 4; t++) {
            n0[t] = (v0 && ch < 3) ? A0[(ch + 1) * 16 + t * 4 + c] : z4;
            n1[t] = (v1 && ch < 3) ? A1[(ch + 1) * 16 + t * 4 + c] : z4;
        }
        #pragma unroll
        for (int t = 0; t < 4; t++) {
            int wnd = ch * 4 + t;
            uint32_t a00 = f2tf32(b0[t].x), a01 = f2tf32(b0[t].y), a02 = f2tf32(b0[t].z), a03 = f2tf32(b0[t].w);
            uint32_t a10 = f2tf32(b1[t].x), a11 = f2tf32(b1[t].y), a12 = f2tf32(b1[t].z), a13 = f2tf32(b1[t].w);
            const uint32_t* bP = sB + (wnd * 8 + 2 * c) * S1P + 2 * g;
            #pragma unroll
            for (int nt = 0; nt < 6; nt++) {
                uint2 bb = *(const uint2*)(bP + 16 * nt);
                mma_tf32(acc[nt], a00, a10, a01, a11, bb.x, bb.y);
            }
            const uint32_t* bQ = bP + S1P;
            #pragma unroll
            for (int nt = 0; nt < 6; nt++) {
                uint2 bb = *(const uint2*)(bQ + 16 * nt);
                mma_tf32(acc[nt], a02, a12, a03, a13, bb.x, bb.y);
            }
        }
        #pragma unroll
        for (int t = 0; t < 4; t++) { b0[t] = n0[t]; b1[t] = n1[t]; }
    }
    #pragma unroll
    for (int nt = 0; nt < 4; nt++) {
        if (v0) ((__half2*)g_h1h)[(size_t)row0 * 16 + nt * 4 + c] = __floats2half2_rn(acc[nt][0], acc[nt][1]);
        if (v1) ((__half2*)g_h1h)[(size_t)row1 * 16 + nt * 4 + c] = __floats2half2_rn(acc[nt][2], acc[nt][3]);
    }
    if (v0) *(float2*)&g_el1[row0 * H1 + 2 * c] = make_float2(acc[4][0], acc[4][1]);
    if (v1) *(float2*)&g_el1[row1 * H1 + 2 * c] = make_float2(acc[4][2], acc[4][3]);
    if (v0) ((__half2*)g_er1h)[(size_t)row0 * 4 + c] = __floats2half2_rn(acc[5][0], acc[5][1]);
    if (v1) ((__half2*)g_er1h)[(size_t)row1 * 4 + c] = __floats2half2_rn(acc[5][2], acc[5][3]);
}

// ---------------- fused scan (decoupled lookback) + scatter ----------------
// 49 blocks x 1024 threads; all co-resident (deadlock-free spins).
__global__ void k_scan_scatter(const int* __restrict__ src, const int* __restrict__ dst) {
    __shared__ int wsum[32];
    __shared__ int soff;
    int n = Nn + 1;
    int tid = threadIdx.x, b = blockIdx.x;
    int gid = b * 1024 + tid;
    int v = (gid < n) ? g_rowptr[gid] : 0;
    int lane = tid & 31, wid = tid >> 5;
    int x = v;
    #pragma unroll
    for (int d = 1; d < 32; d <<= 1) {
        int t = __shfl_up_sync(0xffffffffu, x, d);
        if (lane >= d) x += t;
    }
    if (lane == 31) wsum[wid] = x;
    __syncthreads();
    if (wid == 0) {
        int w = wsum[lane];
        #pragma unroll
        for (int d = 1; d < 32; d <<= 1) {
            int t = __shfl_up_sync(0xffffffffu, w, d);
            if (lane >= d) w += t;
        }
        wsum[lane] = w;
    }
    __syncthreads();
    int incl = x + (wid > 0 ? wsum[wid - 1] : 0);

    // publish block total (tid 1023 holds it)
    if (tid == 1023) atomicExch(&g_bsums[b], incl);

    // lookback: sum totals of preceding blocks
    if (tid < 32) {
        int p1 = 0, p2 = 0;
        if (tid < b)      { volatile int* p = &g_bsums[tid];      int u; do { u = *p; } while (u == -1); p1 = u; }
        if (tid + 32 < b) { volatile int* p = &g_bsums[tid + 32]; int u; do { u = *p; } while (u == -1); p2 = u; }
        int s = p1 + p2;
        #pragma unroll
        for (int d = 16; d > 0; d >>= 1) s += __shfl_xor_sync(0xffffffffu, s, d);
        if (tid == 0) soff = s;
    }
    __syncthreads();
    if (gid < n) {
        int val = soff + incl - v;    // exclusive scan + block offset
        g_rowptr[gid] = val;
        if (gid < Nn) g_cursor[gid] = val;
    }
    __threadfence();
    __syncthreads();
    if (tid == 0) atomicExch(&g_sflag[b], 1);

    // wait for ALL blocks' rowptr/cursor ranges
    if (tid < 49) { volatile int* p = &g_sflag[tid]; while (*p == 0) {} }
    __syncthreads();

    // scatter (grid-stride over edges)
    for (int e = b * 1024 + tid; e < Ee; e += 49 * 1024) {
        int s = src[e];
        int pos = atomicAdd(&g_cursor[s], 1);
        g_csr_dst[pos] = dst[e];
    }
}

// ---------------- layer-1 aggregation (fp16 gathers) -> r1h ----------------
__global__ void k_agg1(const float* __restrict__ b1) {
    __shared__ float ws[8][32 * 8];    // [warp][edge][head]
    int wid = threadIdx.x >> 5, lane = threadIdx.x & 31;
    int i = blockIdx.x * 8 + wid;

    float el_own = (lane < H1) ? g_el1[i * H1 + lane] : 0.f;
    float elh[H1];
    #pragma unroll
    for (int h = 0; h < H1; h++) elh[h] = __shfl_sync(0xffffffffu, el_own, h);

    float acc[H1], denp[H1];
    #pragma unroll
    for (int h = 0; h < H1; h++) { acc[h] = 0.f; denp[h] = 0.f; }

    int beg = g_rowptr[i], end = g_rowptr[i + 1];
    for (int base = beg; base < end; base += 32) {
        int nb = min(32, end - base);
        int dstl = (lane < nb) ? g_csr_dst[base + lane] : 0;
        float w_own[H1];
        if (lane < nb) {
            uint2 rva = *(const uint2*)(g_er1h + (size_t)dstl * H1);
            uint2 rvb = *(const uint2*)(g_er1h + (size_t)dstl * H1 + 4);
            __half2 e0 = *(__half2*)&rva.x, e1 = *(__half2*)&rva.y;
            __half2 e2 = *(__half2*)&rvb.x, e3 = *(__half2*)&rvb.y;
            float er_[H1] = {__low2float(e0), __high2float(e0), __low2float(e1), __high2float(e1),
                             __low2float(e2), __high2float(e2), __low2float(e3), __high2float(e3)};
            #pragma unroll
            for (int h = 0; h < H1; h++) {
                float a = elh[h] + er_[h];
                float lr = a > 0.f ? a : 0.2f * a;
                float wv = __expf(lr);
                w_own[h] = wv;
                denp[h] += wv;
            }
        } else {
            #pragma unroll
            for (int h = 0; h < H1; h++) w_own[h] = 0.f;
        }
        float4* wrow = (float4*)&ws[wid][lane * 8];
        wrow[0] = make_float4(w_own[0], w_own[1], w_own[2], w_own[3]);
        wrow[1] = make_float4(w_own[4], w_own[5], w_own[6], w_own[7]);
        __syncwarp();
        for (int j = 0; j < nb; j += 8) {
            int dd[8];
            #pragma unroll
            for (int u = 0; u < 8; u++) dd[u] = __shfl_sync(0xffffffffu, dstl, j + u);
            float hv[8];
            #pragma unroll
            for (int u = 0; u < 8; u++) hv[u] = __half2float(g_h1h[(size_t)dd[u] * F1 + lane]);
            const float4* wj = (const float4*)&ws[wid][j * 8];
            #pragma unroll
            for (int u = 0; u < 8; u++) {
                float4 wa = wj[u * 2], wb = wj[u * 2 + 1];
                acc[0] = fmaf(wa.x, hv[u], acc[0]);
                acc[1] = fmaf(wa.y, hv[u], acc[1]);
                acc[2] = fmaf(wa.z, hv[u], acc[2]);
                acc[3] = fmaf(wa.w, hv[u], acc[3]);
                acc[4] = fmaf(wb.x, hv[u], acc[4]);
                acc[5] = fmaf(wb.y, hv[u], acc[5]);
                acc[6] = fmaf(wb.z, hv[u], acc[6]);
                acc[7] = fmaf(wb.w, hv[u], acc[7]);
            }
        }
        __syncwarp();
    }
    float bb = b1[lane];
    #pragma unroll
    for (int h = 0; h < H1; h++) {
        float t = denp[h];
        #pragma unroll
        for (int d = 16; d > 0; d >>= 1) t += __shfl_xor_sync(0xffffffffu, t, d);
        float o = acc[h] / fmaxf(t, 1e-12f) + bb;
        float e = o > 0.f ? o : (__expf(o) - 1.f);   // ELU
        g_r1h[(size_t)i * NHID + h * F1 + lane] = __float2half(e);
    }
}

// ---------------- GEMM2 (tf32, fused B prep, fp16 A from r1h) ----------------
#define S2P 116
__global__ void __launch_bounds__(256) k_gemm2(const float* __restrict__ W2,
                                               const float* __restrict__ Wl2,
                                               const float* __restrict__ Wr2) {
    extern __shared__ uint32_t sm2[];
    uint32_t* sB = sm2;                      // [128][S2P]
    __shared__ float swl2[NC], swr2[NC];
    int tx = threadIdx.x, lane = tx & 31, w = tx >> 5;
    if (tx < NC) { swl2[tx] = Wl2[tx]; swr2[tx] = Wr2[tx]; }
    __syncthreads();
    {
        int k = tx;
        float sl = 0.f, sr = 0.f;
        #pragma unroll 4
        for (int j = 0; j < NC; j++) {
            float v = W2[k * NC + j];
            sB[(k >> 1) * S2P + 2 * j + (k & 1)] = f2tf32(v);
            sl = fmaf(v, swl2[j], sl);
            sr = fmaf(v, swr2[j], sr);
        }
        sB[(k >> 1) * S2P + 2 * 47 + (k & 1)] = 0u;
        sB[(k >> 1) * S2P + 2 * 48 + (k & 1)] = f2tf32(sl);
        sB[(k >> 1) * S2P + 2 * 49 + (k & 1)] = f2tf32(sr);
        #pragma unroll
        for (int j = 50; j < 56; j++) sB[(k >> 1) * S2P + 2 * j + (k & 1)] = 0u;
    }
    __syncthreads();

    int g = lane >> 2, c = lane & 3;
    int row0 = blockIdx.x * 128 + w * 16 + g;
    int row1 = row0 + 8;
    bool v0 = row0 < Nn, v1 = row1 < Nn;
    const uint2* A0 = (const uint2*)(g_r1h + (size_t)row0 * FIN);
    const uint2* A1 = (const uint2*)(g_r1h + (size_t)row1 * FIN);
    const uint2 z2 = make_uint2(0u, 0u);

    float acc[7][4];
    #pragma unroll
    for (int nt = 0; nt < 7; nt++)
        #pragma unroll
        for (int j = 0; j < 4; j++) acc[nt][j] = 0.f;

    uint2 b0[4], b1[4];
    #pragma unroll
    for (int t = 0; t < 4; t++) {
        b0[t] = v0 ? A0[t * 4 + c] : z2;
        b1[t] = v1 ? A1[t * 4 + c] : z2;
    }
    #pragma unroll
    for (int ch = 0; ch < 4; ch++) {
        uint2 n0[4], n1[4];
        #pragma unroll
        for (int t = 0; t < 4; t++) {
            n0[t] = (v0 && ch < 3) ? A0[(ch + 1) * 16 + t * 4 + c] : z2;
            n1[t] = (v1 && ch < 3) ? A1[(ch + 1) * 16 + t * 4 + c] : z2;
        }
        #pragma unroll
        for (int t = 0; t < 4; t++) {
            int wnd = ch * 4 + t;
            float4 fa0 = h4_to_f4(b0[t]);
            float4 fa1 = h4_to_f4(b1[t]);
            uint32_t a00 = f2tf32(fa0.x), a01 = f2tf32(fa0.y), a02 = f2tf32(fa0.z), a03 = f2tf32(fa0.w);
            uint32_t a10 = f2tf32(fa1.x), a11 = f2tf32(fa1.y), a12 = f2tf32(fa1.z), a13 = f2tf32(fa1.w);
            const uint32_t* bP = sB + (wnd * 8 + 2 * c) * S2P + 2 * g;
            #pragma unroll
            for (int nt = 0; nt < 7; nt++) {
                uint2 bb = *(const uint2*)(bP + 16 * nt);
                mma_tf32(acc[nt], a00, a10, a01, a11, bb.x, bb.y);
            }
            const uint32_t* bQ = bP + S2P;
            #pragma unroll
            for (int nt = 0; nt < 7; nt++) {
                uint2 bb = *(const uint2*)(bQ + 16 * nt);
                mma_tf32(acc[nt], a02, a12, a03, a13, bb.x, bb.y);
            }
        }
        #pragma unroll
        for (int t = 0; t < 4; t++) { b0[t] = n0[t]; b1[t] = n1[t]; }
    }
    #pragma unroll
    for (int nt = 0; nt < 7; nt++) {
        int col = nt * 8 + 2 * c;
        if (col < 48) {
            if (v0) ((__half2*)g_h2ph)[(size_t)row0 * 24 + nt * 4 + c] = __floats2half2_rn(acc[nt][0], acc[nt][1]);
            if (v1) ((__half2*)g_h2ph)[(size_t)row1 * 24 + nt * 4 + c] = __floats2half2_rn(acc[nt][2], acc[nt][3]);
        } else if (col == 48) {
            if (v0) { g_el2[row0] = acc[nt][0]; g_er2[row0] = acc[nt][1]; }
            if (v1) { g_el2[row1] = acc[nt][2]; g_er2[row1] = acc[nt][3]; }
        }
    }
}

// ---------------- layer-2 aggregation (fp16 gathers) + log_softmax ----------------
__global__ void k_agg2(const float* __restrict__ b2, float* __restrict__ out) {
    int wid = threadIdx.x >> 5, lane = threadIdx.x & 31;
    int i = blockIdx.x * 8 + wid;
    float el = g_el2[i];
    float accx = 0.f, accy = 0.f, denp = 0.f;
    int beg = g_rowptr[i], end = g_rowptr[i + 1];
    for (int base = beg; base < end; base += 32) {
        int nb = min(32, end - base);
        int dstl = (lane < nb) ? g_csr_dst[base + lane] : 0;
        float wl_ = 0.f;
        if (lane < nb) {
            float a = el + g_er2[dstl];
            float lr = a > 0.f ? a : 0.2f * a;
            wl_ = __expf(lr);
            denp += wl_;
        }
        for (int j = 0; j < nb; j += 8) {
            int dd[8];
            float wv[8];
            #pragma unroll
            for (int u = 0; u < 8; u++) {
                dd[u] = __shfl_sync(0xffffffffu, dstl, j + u);
                wv[u] = __shfl_sync(0xffffffffu, wl_, j + u);
            }
            if (lane < 24) {
                __half2 hh[8];
                #pragma unroll
                for (int u = 0; u < 8; u++)
                    hh[u] = ((const __half2*)g_h2ph)[(size_t)dd[u] * 24 + lane];
                #pragma unroll
                for (int u = 0; u < 8; u++) {
                    accx = fmaf(wv[u], __low2float(hh[u]), accx);
                    accy = fmaf(wv[u], __high2float(hh[u]), accy);
                }
            }
        }
    }
    float den = denp;
    #pragma unroll
    for (int d = 16; d > 0; d >>= 1) den += __shfl_xor_sync(0xffffffffu, den, d);
    den = fmaxf(den, 1e-12f);
    float vx = -3.0e38f, vy = -3.0e38f;
    if (lane < 24) {
        vx = accx / den + b2[2 * lane];
        vy = (2 * lane + 1 < NC) ? (accy / den + b2[2 * lane + 1]) : -3.0e38f;
    }
    float m = fmaxf(vx, vy);
    #pragma unroll
    for (int d = 16; d > 0; d >>= 1) m = fmaxf(m, __shfl_xor_sync(0xffffffffu, m, d));
    float s = 0.f;
    if (lane < 24) {
        s = __expf(vx - m);
        if (2 * lane + 1 < NC) s += __expf(vy - m);
    }
    #pragma unroll
    for (int d = 16; d > 0; d >>= 1) s += __shfl_xor_sync(0xffffffffu, s, d);
    float ls = logf(s);
    if (lane < 24) {
        out[(size_t)i * NC + 2 * lane] = vx - m - ls;
        if (2 * lane + 1 < NC) out[(size_t)i * NC + 2 * lane + 1] = vy - m - ls;
    }
}

// ---------------- launch (6 kernels; #4 = k_agg1 -> profiled) ----------------
extern "C" void kernel_launch(void* const* d_in, const int* in_sizes, int n_in,
                              void* d_out, int out_size) {
    const float* x    = (const float*)d_in[0];
    const int*   esrc = (const int*)  d_in[1];
    const int*   edst = (const int*)  d_in[2];
    const float* W1   = (const float*)d_in[3];
    const float* Wl1  = (const float*)d_in[4];
    const float* Wr1  = (const float*)d_in[5];
    const float* b1   = (const float*)d_in[6];
    const float* W2   = (const float*)d_in[7];
    const float* Wl2  = (const float*)d_in[8];
    const float* Wr2  = (const float*)d_in[9];
    const float* b2   = (const float*)d_in[10];
    float* out = (float*)d_out;

    const int smem1 = 128 * S1P * 4;   // 51.2 KB
    const int smem2 = 128 * S2P * 4;   // 59.4 KB
    cudaFuncSetAttribute(k_gemm1, cudaFuncAttributeMaxDynamicSharedMemorySize, smem1);
    cudaFuncSetAttribute(k_gemm2, cudaFuncAttributeMaxDynamicSharedMemorySize, smem2);

    k_zero<<<(Nn + 1 + 255) / 256, 256>>>();
    k_gemm1<<<(Nn + 127) / 128, 256, smem1>>>(x, W1, Wl1, Wr1, esrc);
    k_scan_scatter<<<49, 1024>>>(esrc, edst);
    k_agg1<<<Nn / 8, 256>>>(b1);                    // #4 <- profiled
    k_gemm2<<<(Nn + 127) / 128, 256, smem2>>>(W2, Wl2, Wr2);
    k_agg2<<<Nn / 8, 256>>>(b2, out);
}

// round 12
// speedup vs baseline: 1.4830x; 1.0428x over previous
#include <cuda_runtime.h>
#include <cuda_fp16.h>
#include <cstdint>

#define Nn 50000
#define Ee 800000
#define FIN 256
#define F1 32
#define H1 8
#define NHID 256
#define NC 47

// ---------------- scratch (device globals: allocation-free) ----------------
__device__ int    g_rowptr[Nn + 1];
__device__ int    g_cursor[Nn];
__device__ int    g_csr_dst[Ee];
__device__ int    g_bsums[64];
__device__ int    g_sflag[64];
__device__ __half g_h1h[Nn * F1];        // 3.2 MB fp16 gather array (layer 1)
__device__ float  g_el1[Nn * H1];
__device__ __half g_er1h[Nn * H1];       // 0.8 MB fp16 gather array
__device__ __half g_r1h[Nn * NHID];      // 25.6 MB fp16 hidden activations
__device__ __half g_h2ph[Nn * 48];       // 4.8 MB fp16 gather array (layer 2)
__device__ float  g_el2[Nn];
__device__ float  g_er2[Nn];

// ---------------- tf32 mma helpers ----------------
__device__ __forceinline__ uint32_t f2tf32(float f) {
    uint32_t r;
    asm("cvt.rna.tf32.f32 %0, %1;" : "=r"(r) : "f"(f));
    return r;
}

__device__ __forceinline__ void mma_tf32(float* d,
    uint32_t a0, uint32_t a1, uint32_t a2, uint32_t a3,
    uint32_t b0, uint32_t b1) {
    asm volatile(
        "mma.sync.aligned.m16n8k8.row.col.f32.tf32.tf32.f32 "
        "{%0,%1,%2,%3},{%4,%5,%6,%7},{%8,%9},{%0,%1,%2,%3};\n"
        : "+f"(d[0]), "+f"(d[1]), "+f"(d[2]), "+f"(d[3])
        : "r"(a0), "r"(a1), "r"(a2), "r"(a3), "r"(b0), "r"(b1));
}

__device__ __forceinline__ float4 h4_to_f4(uint2 r) {
    __half2 p0 = *(__half2*)&r.x, p1 = *(__half2*)&r.y;
    return make_float4(__low2float(p0), __high2float(p0),
                       __low2float(p1), __high2float(p1));
}

// ---------------- zero / sentinel init ----------------
__global__ void k_zero() {
    int i = blockIdx.x * 256 + threadIdx.x;
    if (i < Nn + 1) g_rowptr[i] = 0;
    if (i < 64) { g_bsums[i] = -1; g_sflag[i] = 0; }
}

// ---------------- GEMM1 (tf32, fused: edge count + B prep + MMA) ----------------
#define S1P 100
__global__ void __launch_bounds__(256) k_gemm1(const float* __restrict__ x,
                                               const float* __restrict__ W1,
                                               const float* __restrict__ Wl1,
                                               const float* __restrict__ Wr1,
                                               const int* __restrict__ esrc) {
    extern __shared__ uint32_t sm1[];
    uint32_t* sB = sm1;                      // [128][S1P] pair-interleaved
    __shared__ float swl[F1 * H1], swr[F1 * H1];
    int tx = threadIdx.x, lane = tx & 31, w = tx >> 5;

    for (int e = blockIdx.x * 256 + tx; e < Ee; e += gridDim.x * 256)
        atomicAdd(&g_rowptr[esrc[e]], 1);

    for (int i = tx; i < FIN * F1; i += 256) {
        int k = i >> 5, n = i & 31;
        sB[(k >> 1) * S1P + 2 * n + (k & 1)] = f2tf32(W1[i]);
    }
    swl[tx] = Wl1[tx];
    swr[tx] = Wr1[tx];
    __syncthreads();

    {
        int k = tx;
        float sl[H1], sr[H1];
        #pragma unroll
        for (int h = 0; h < H1; h++) { sl[h] = 0.f; sr[h] = 0.f; }
        #pragma unroll 8
        for (int j = 0; j < F1; j++) {
            float v = __uint_as_float(sB[(k >> 1) * S1P + 2 * j + (k & 1)]);
            #pragma unroll
            for (int h = 0; h < H1; h++) {
                sl[h] = fmaf(v, swl[j * H1 + h], sl[h]);
                sr[h] = fmaf(v, swr[j * H1 + h], sr[h]);
            }
        }
        #pragma unroll
        for (int h = 0; h < H1; h++) {
            sB[(k >> 1) * S1P + 2 * (32 + h) + (k & 1)] = f2tf32(sl[h]);
            sB[(k >> 1) * S1P + 2 * (40 + h) + (k & 1)] = f2tf32(sr[h]);
        }
    }
    __syncthreads();

    int g = lane >> 2, c = lane & 3;
    int row0 = blockIdx.x * 128 + w * 16 + g;
    int row1 = row0 + 8;
    bool v0 = row0 < Nn, v1 = row1 < Nn;
    const float4* A0 = (const float4*)(x + (size_t)row0 * FIN);
    const float4* A1 = (const float4*)(x + (size_t)row1 * FIN);
    const float4 z4 = make_float4(0.f, 0.f, 0.f, 0.f);

    float acc[6][4];
    #pragma unroll
    for (int nt = 0; nt < 6; nt++)
        #pragma unroll
        for (int j = 0; j < 4; j++) acc[nt][j] = 0.f;

    float4 b0[4], b1[4];
    #pragma unroll
    for (int t = 0; t < 4; t++) {
        b0[t] = v0 ? A0[t * 4 + c] : z4;
        b1[t] = v1 ? A1[t * 4 + c] : z4;
    }
    #pragma unroll
    for (int ch = 0; ch < 4; ch++) {
        float4 n0[4], n1[4];
        #pragma unroll
        for (int t = 0; t < 4; t++) {
            n0[t] = (v0 && ch < 3) ? A0[(ch + 1) * 16 + t * 4 + c] : z4;
            n1[t] = (v1 && ch < 3) ? A1[(ch + 1) * 16 + t * 4 + c] : z4;
        }
        #pragma unroll
        for (int t = 0; t < 4; t++) {
            int wnd = ch * 4 + t;
            uint32_t a00 = f2tf32(b0[t].x), a01 = f2tf32(b0[t].y), a02 = f2tf32(b0[t].z), a03 = f2tf32(b0[t].w);
            uint32_t a10 = f2tf32(b1[t].x), a11 = f2tf32(b1[t].y), a12 = f2tf32(b1[t].z), a13 = f2tf32(b1[t].w);
            const uint32_t* bP = sB + (wnd * 8 + 2 * c) * S1P + 2 * g;
            #pragma unroll
            for (int nt = 0; nt < 6; nt++) {
                uint2 bb = *(const uint2*)(bP + 16 * nt);
                mma_tf32(acc[nt], a00, a10, a01, a11, bb.x, bb.y);
            }
            const uint32_t* bQ = bP + S1P;
            #pragma unroll
            for (int nt = 0; nt < 6; nt++) {
                uint2 bb = *(const uint2*)(bQ + 16 * nt);
                mma_tf32(acc[nt], a02, a12, a03, a13, bb.x, bb.y);
            }
        }
        #pragma unroll
        for (int t = 0; t < 4; t++) { b0[t] = n0[t]; b1[t] = n1[t]; }
    }
    #pragma unroll
    for (int nt = 0; nt < 4; nt++) {
        if (v0) ((__half2*)g_h1h)[(size_t)row0 * 16 + nt * 4 + c] = __floats2half2_rn(acc[nt][0], acc[nt][1]);
        if (v1) ((__half2*)g_h1h)[(size_t)row1 * 16 + nt * 4 + c] = __floats2half2_rn(acc[nt][2], acc[nt][3]);
    }
    if (v0) *(float2*)&g_el1[row0 * H1 + 2 * c] = make_float2(acc[4][0], acc[4][1]);
    if (v1) *(float2*)&g_el1[row1 * H1 + 2 * c] = make_float2(acc[4][2], acc[4][3]);
    if (v0) ((__half2*)g_er1h)[(size_t)row0 * 4 + c] = __floats2half2_rn(acc[5][0], acc[5][1]);
    if (v1) ((__half2*)g_er1h)[(size_t)row1 * 4 + c] = __floats2half2_rn(acc[5][2], acc[5][3]);
}

// ---------------- fused scan (decoupled lookback) + scatter ----------------
__global__ void k_scan_scatter(const int* __restrict__ src, const int* __restrict__ dst) {
    __shared__ int wsum[32];
    __shared__ int soff;
    int n = Nn + 1;
    int tid = threadIdx.x, b = blockIdx.x;
    int gid = b * 1024 + tid;
    int v = (gid < n) ? g_rowptr[gid] : 0;
    int lane = tid & 31, wid = tid >> 5;
    int x = v;
    #pragma unroll
    for (int d = 1; d < 32; d <<= 1) {
        int t = __shfl_up_sync(0xffffffffu, x, d);
        if (lane >= d) x += t;
    }
    if (lane == 31) wsum[wid] = x;
    __syncthreads();
    if (wid == 0) {
        int w = wsum[lane];
        #pragma unroll
        for (int d = 1; d < 32; d <<= 1) {
            int t = __shfl_up_sync(0xffffffffu, w, d);
            if (lane >= d) w += t;
        }
        wsum[lane] = w;
    }
    __syncthreads();
    int incl = x + (wid > 0 ? wsum[wid - 1] : 0);

    if (tid == 1023) atomicExch(&g_bsums[b], incl);

    if (tid < 32) {
        int p1 = 0, p2 = 0;
        if (tid < b)      { volatile int* p = &g_bsums[tid];      int u; do { u = *p; } while (u == -1); p1 = u; }
        if (tid + 32 < b) { volatile int* p = &g_bsums[tid + 32]; int u; do { u = *p; } while (u == -1); p2 = u; }
        int s = p1 + p2;
        #pragma unroll
        for (int d = 16; d > 0; d >>= 1) s += __shfl_xor_sync(0xffffffffu, s, d);
        if (tid == 0) soff = s;
    }
    __syncthreads();
    if (gid < n) {
        int val = soff + incl - v;
        g_rowptr[gid] = val;
        if (gid < Nn) g_cursor[gid] = val;
    }
    __threadfence();
    __syncthreads();
    if (tid == 0) atomicExch(&g_sflag[b], 1);

    if (tid < 49) { volatile int* p = &g_sflag[tid]; while (*p == 0) {} }
    __syncthreads();

    for (int e = b * 1024 + tid; e < Ee; e += 49 * 1024) {
        int s = src[e];
        int pos = atomicAdd(&g_cursor[s], 1);
        g_csr_dst[pos] = dst[e];
    }
}

// ---------------- layer-1 aggregation (dual-edge half2 gathers) -> r1h ----------------
// lane = (half-warp hw, feature-pair p): hw=0 handles even edges, hw=1 odd.
// Per edge-pair: 1 LDG(half2) + 2 LDS.128 + 16 FMA + 1 shfl (vs 2/4/16/2 before).
__global__ void __launch_bounds__(256) k_agg1(const float* __restrict__ b1) {
    __shared__ float ws[8][32 * 8];    // [warp][edge][head], zero-filled tails
    int wid = threadIdx.x >> 5, lane = threadIdx.x & 31;
    int i = blockIdx.x * 8 + wid;
    int hw = lane >> 4;                // 0 / 1
    int p  = lane & 15;                // feature pair 0..15

    float el_own = (lane < H1) ? g_el1[i * H1 + lane] : 0.f;
    float elh[H1];
    #pragma unroll
    for (int h = 0; h < H1; h++) elh[h] = __shfl_sync(0xffffffffu, el_own, h);

    float accx[H1], accy[H1], denp[H1];
    #pragma unroll
    for (int h = 0; h < H1; h++) { accx[h] = 0.f; accy[h] = 0.f; denp[h] = 0.f; }

    int beg = g_rowptr[i], end = g_rowptr[i + 1];
    const __half2* __restrict__ h1h2 = (const __half2*)g_h1h;
    for (int base = beg; base < end; base += 32) {
        int nb = min(32, end - base);
        int dstl = (lane < nb) ? g_csr_dst[base + lane] : 0;
        float w_own[H1];
        if (lane < nb) {
            uint2 rva = *(const uint2*)(g_er1h + dstl * H1);
            uint2 rvb = *(const uint2*)(g_er1h + dstl * H1 + 4);
            __half2 e0 = *(__half2*)&rva.x, e1 = *(__half2*)&rva.y;
            __half2 e2 = *(__half2*)&rvb.x, e3 = *(__half2*)&rvb.y;
            float er_[H1] = {__low2float(e0), __high2float(e0), __low2float(e1), __high2float(e1),
                             __low2float(e2), __high2float(e2), __low2float(e3), __high2float(e3)};
            #pragma unroll
            for (int h = 0; h < H1; h++) {
                float a = elh[h] + er_[h];
                float lr = a > 0.f ? a : 0.2f * a;
                float wv = __expf(lr);
                w_own[h] = wv;
                denp[h] += wv;
            }
        } else {
            #pragma unroll
            for (int h = 0; h < H1; h++) w_own[h] = 0.f;
        }
        float4* wrow = (float4*)&ws[wid][lane * 8];
        wrow[0] = make_float4(w_own[0], w_own[1], w_own[2], w_own[3]);
        wrow[1] = make_float4(w_own[4], w_own[5], w_own[6], w_own[7]);
        __syncwarp();
        int nbp = (nb + 1) >> 1;     // edge pairs
        for (int j2 = 0; j2 < nbp; j2 += 8) {
            int ee[8], de[8];
            #pragma unroll
            for (int u = 0; u < 8; u++) {
                ee[u] = 2 * (j2 + u) + hw;                         // my edge (≤31)
                de[u] = __shfl_sync(0xffffffffu, dstl, ee[u]);
            }
            __half2 hh[8];
            #pragma unroll
            for (int u = 0; u < 8; u++)
                hh[u] = h1h2[de[u] * 16 + p];
            #pragma unroll
            for (int u = 0; u < 8; u++) {
                float hx = __low2float(hh[u]), hy = __high2float(hh[u]);
                const float4* wj = (const float4*)&ws[wid][ee[u] * 8];
                float4 wa = wj[0], wb = wj[1];
                accx[0] = fmaf(wa.x, hx, accx[0]); accy[0] = fmaf(wa.x, hy, accy[0]);
                accx[1] = fmaf(wa.y, hx, accx[1]); accy[1] = fmaf(wa.y, hy, accy[1]);
                accx[2] = fmaf(wa.z, hx, accx[2]); accy[2] = fmaf(wa.z, hy, accy[2]);
                accx[3] = fmaf(wa.w, hx, accx[3]); accy[3] = fmaf(wa.w, hy, accy[3]);
                accx[4] = fmaf(wb.x, hx, accx[4]); accy[4] = fmaf(wb.x, hy, accy[4]);
                accx[5] = fmaf(wb.y, hx, accx[5]); accy[5] = fmaf(wb.y, hy, accy[5]);
                accx[6] = fmaf(wb.z, hx, accx[6]); accy[6] = fmaf(wb.z, hy, accy[6]);
                accx[7] = fmaf(wb.w, hx, accx[7]); accy[7] = fmaf(wb.w, hy, accy[7]);
            }
        }
        __syncwarp();
    }
    // combine even/odd halves (feature pair p identical across halves)
    #pragma unroll
    for (int h = 0; h < H1; h++) {
        accx[h] += __shfl_xor_sync(0xffffffffu, accx[h], 16);
        accy[h] += __shfl_xor_sync(0xffffffffu, accy[h], 16);
    }
    float2 bb = ((const float2*)b1)[p];
    __half2* r1h2 = (__half2*)g_r1h;
    #pragma unroll
    for (int h = 0; h < H1; h++) {
        float t = denp[h];
        #pragma unroll
        for (int d = 16; d > 0; d >>= 1) t += __shfl_xor_sync(0xffffffffu, t, d);
        float rden = __fdividef(1.f, fmaxf(t, 1e-12f));
        float o0 = fmaf(accx[h], rden, bb.x);
        float o1 = fmaf(accy[h], rden, bb.y);
        float e0 = o0 > 0.f ? o0 : (__expf(o0) - 1.f);
        float e1 = o1 > 0.f ? o1 : (__expf(o1) - 1.f);
        // hw=0 writes heads 0..3, hw=1 writes heads 4..7
        if ((h >> 2) == hw)
            r1h2[i * 128 + h * 16 + p] = __floats2half2_rn(e0, e1);
    }
}

// ---------------- GEMM2 (tf32, fused B prep, fp16 A from r1h) ----------------
#define S2P 116
__global__ void __launch_bounds__(256) k_gemm2(const float* __restrict__ W2,
                                               const float* __restrict__ Wl2,
                                               const float* __restrict__ Wr2) {
    extern __shared__ uint32_t sm2[];
    uint32_t* sB = sm2;                      // [128][S2P]
    __shared__ float swl2[NC], swr2[NC];
    int tx = threadIdx.x, lane = tx & 31, w = tx >> 5;
    if (tx < NC) { swl2[tx] = Wl2[tx]; swr2[tx] = Wr2[tx]; }
    __syncthreads();
    {
        int k = tx;
        float sl = 0.f, sr = 0.f;
        #pragma unroll 4
        for (int j = 0; j < NC; j++) {
            float v = W2[k * NC + j];
            sB[(k >> 1) * S2P + 2 * j + (k & 1)] = f2tf32(v);
            sl = fmaf(v, swl2[j], sl);
            sr = fmaf(v, swr2[j], sr);
        }
        sB[(k >> 1) * S2P + 2 * 47 + (k & 1)] = 0u;
        sB[(k >> 1) * S2P + 2 * 48 + (k & 1)] = f2tf32(sl);
        sB[(k >> 1) * S2P + 2 * 49 + (k & 1)] = f2tf32(sr);
        #pragma unroll
        for (int j = 50; j < 56; j++) sB[(k >> 1) * S2P + 2 * j + (k & 1)] = 0u;
    }
    __syncthreads();

    int g = lane >> 2, c = lane & 3;
    int row0 = blockIdx.x * 128 + w * 16 + g;
    int row1 = row0 + 8;
    bool v0 = row0 < Nn, v1 = row1 < Nn;
    const uint2* A0 = (const uint2*)(g_r1h + (size_t)row0 * FIN);
    const uint2* A1 = (const uint2*)(g_r1h + (size_t)row1 * FIN);
    const uint2 z2 = make_uint2(0u, 0u);

    float acc[7][4];
    #pragma unroll
    for (int nt = 0; nt < 7; nt++)
        #pragma unroll
        for (int j = 0; j < 4; j++) acc[nt][j] = 0.f;

    uint2 b0[4], b1[4];
    #pragma unroll
    for (int t = 0; t < 4; t++) {
        b0[t] = v0 ? A0[t * 4 + c] : z2;
        b1[t] = v1 ? A1[t * 4 + c] : z2;
    }
    #pragma unroll
    for (int ch = 0; ch < 4; ch++) {
        uint2 n0[4], n1[4];
        #pragma unroll
        for (int t = 0; t < 4; t++) {
            n0[t] = (v0 && ch < 3) ? A0[(ch + 1) * 16 + t * 4 + c] : z2;
            n1[t] = (v1 && ch < 3) ? A1[(ch + 1) * 16 + t * 4 + c] : z2;
        }
        #pragma unroll
        for (int t = 0; t < 4; t++) {
            int wnd = ch * 4 + t;
            float4 fa0 = h4_to_f4(b0[t]);
            float4 fa1 = h4_to_f4(b1[t]);
            uint32_t a00 = f2tf32(fa0.x), a01 = f2tf32(fa0.y), a02 = f2tf32(fa0.z), a03 = f2tf32(fa0.w);
            uint32_t a10 = f2tf32(fa1.x), a11 = f2tf32(fa1.y), a12 = f2tf32(fa1.z), a13 = f2tf32(fa1.w);
            const uint32_t* bP = sB + (wnd * 8 + 2 * c) * S2P + 2 * g;
            #pragma unroll
            for (int nt = 0; nt < 7; nt++) {
                uint2 bb = *(const uint2*)(bP + 16 * nt);
                mma_tf32(acc[nt], a00, a10, a01, a11, bb.x, bb.y);
            }
            const uint32_t* bQ = bP + S2P;
            #pragma unroll
            for (int nt = 0; nt < 7; nt++) {
                uint2 bb = *(const uint2*)(bQ + 16 * nt);
                mma_tf32(acc[nt], a02, a12, a03, a13, bb.x, bb.y);
            }
        }
        #pragma unroll
        for (int t = 0; t < 4; t++) { b0[t] = n0[t]; b1[t] = n1[t]; }
    }
    #pragma unroll
    for (int nt = 0; nt < 7; nt++) {
        int col = nt * 8 + 2 * c;
        if (col < 48) {
            if (v0) ((__half2*)g_h2ph)[(size_t)row0 * 24 + nt * 4 + c] = __floats2half2_rn(acc[nt][0], acc[nt][1]);
            if (v1) ((__half2*)g_h2ph)[(size_t)row1 * 24 + nt * 4 + c] = __floats2half2_rn(acc[nt][2], acc[nt][3]);
        } else if (col == 48) {
            if (v0) { g_el2[row0] = acc[nt][0]; g_er2[row0] = acc[nt][1]; }
            if (v1) { g_el2[row1] = acc[nt][2]; g_er2[row1] = acc[nt][3]; }
        }
    }
}

// ---------------- layer-2 aggregation (fp16 gathers) + log_softmax ----------------
__global__ void __launch_bounds__(256) k_agg2(const float* __restrict__ b2, float* __restrict__ out) {
    int wid = threadIdx.x >> 5, lane = threadIdx.x & 31;
    int i = blockIdx.x * 8 + wid;
    float el = g_el2[i];
    float accx = 0.f, accy = 0.f, denp = 0.f;
    int beg = g_rowptr[i], end = g_rowptr[i + 1];
    const __half2* __restrict__ h2p2 = (const __half2*)g_h2ph;
    for (int base = beg; base < end; base += 32) {
        int nb = min(32, end - base);
        int dstl = (lane < nb) ? g_csr_dst[base + lane] : 0;
        float wl_ = 0.f;
        if (lane < nb) {
            float a = el + g_er2[dstl];
            float lr = a > 0.f ? a : 0.2f * a;
            wl_ = __expf(lr);
            denp += wl_;
        }
        for (int j = 0; j < nb; j += 8) {
            int dd[8];
            float wv[8];
            #pragma unroll
            for (int u = 0; u < 8; u++) {
                dd[u] = __shfl_sync(0xffffffffu, dstl, j + u);
                wv[u] = __shfl_sync(0xffffffffu, wl_, j + u);
            }
            if (lane < 24) {
                __half2 hh[8];
                #pragma unroll
                for (int u = 0; u < 8; u++)
                    hh[u] = h2p2[dd[u] * 24 + lane];
                #pragma unroll
                for (int u = 0; u < 8; u++) {
                    accx = fmaf(wv[u], __low2float(hh[u]), accx);
                    accy = fmaf(wv[u], __high2float(hh[u]), accy);
                }
            }
        }
    }
    float den = denp;
    #pragma unroll
    for (int d = 16; d > 0; d >>= 1) den += __shfl_xor_sync(0xffffffffu, den, d);
    float rden = __fdividef(1.f, fmaxf(den, 1e-12f));
    float vx = -3.0e38f, vy = -3.0e38f;
    if (lane < 24) {
        vx = fmaf(accx, rden, b2[2 * lane]);
        vy = (2 * lane + 1 < NC) ? fmaf(accy, rden, b2[2 * lane + 1]) : -3.0e38f;
    }
    float m = fmaxf(vx, vy);
    #pragma unroll
    for (int d = 16; d > 0; d >>= 1) m = fmaxf(m, __shfl_xor_sync(0xffffffffu, m, d));
    float s = 0.f;
    if (lane < 24) {
        s = __expf(vx - m);
        if (2 * lane + 1 < NC) s += __expf(vy - m);
    }
    #pragma unroll
    for (int d = 16; d > 0; d >>= 1) s += __shfl_xor_sync(0xffffffffu, s, d);
    float ls = logf(s);
    if (lane < 24) {
        out[(size_t)i * NC + 2 * lane] = vx - m - ls;
        if (2 * lane + 1 < NC) out[(size_t)i * NC + 2 * lane + 1] = vy - m - ls;
    }
}

// ---------------- launch (6 kernels; #4 = k_agg1 -> profiled) ----------------
extern "C" void kernel_launch(void* const* d_in, const int* in_sizes, int n_in,
                              void* d_out, int out_size) {
    const float* x    = (const float*)d_in[0];
    const int*   esrc = (const int*)  d_in[1];
    const int*   edst = (const int*)  d_in[2];
    const float* W1   = (const float*)d_in[3];
    const float* Wl1  = (const float*)d_in[4];
    const float* Wr1  = (const float*)d_in[5];
    const float* b1   = (const float*)d_in[6];
    const float* W2   = (const float*)d_in[7];
    const float* Wl2  = (const float*)d_in[8];
    const float* Wr2  = (const float*)d_in[9];
    const float* b2   = (const float*)d_in[10];
    float* out = (float*)d_out;

    const int smem1 = 128 * S1P * 4;   // 51.2 KB
    const int smem2 = 128 * S2P * 4;   // 59.4 KB
    cudaFuncSetAttribute(k_gemm1, cudaFuncAttributeMaxDynamicSharedMemorySize, smem1);
    cudaFuncSetAttribute(k_gemm2, cudaFuncAttributeMaxDynamicSharedMemorySize, smem2);

    k_zero<<<(Nn + 1 + 255) / 256, 256>>>();
    k_gemm1<<<(Nn + 127) / 128, 256, smem1>>>(x, W1, Wl1, Wr1, esrc);
    k_scan_scatter<<<49, 1024>>>(esrc, edst);
    k_agg1<<<Nn / 8, 256>>>(b1);                    // #4 <- profiled
    k_gemm2<<<(Nn + 127) / 128, 256, smem2>>>(W2, Wl2, Wr2);
    k_agg2<<<Nn / 8, 256>>>(b2, out);
}

// round 13
// speedup vs baseline: 1.5921x; 1.0735x over previous
#include <cuda_runtime.h>
#include <cuda_fp16.h>
#include <cstdint>

#define Nn 50000
#define Ee 800000
#define FIN 256
#define F1 32
#define H1 8
#define NHID 256
#define NC 47

// ---------------- scratch (device globals: allocation-free) ----------------
__device__ int    g_rowptr[Nn + 1];
__device__ int    g_cursor[Nn];
__device__ int    g_csr_dst[Ee];
__device__ int    g_bsums[64];
__device__ int    g_sflag[64];
__device__ __half g_h1h[Nn * F1];        // 3.2 MB fp16 gather array (layer 1)
__device__ float  g_el1[Nn * H1];
__device__ __half g_er1h[Nn * H1];       // 0.8 MB fp16 gather array
__device__ __half g_r1h[Nn * NHID];      // 25.6 MB fp16 hidden activations
__device__ __half g_h2ph[Nn * 48];       // 4.8 MB fp16 gather array (layer 2)
__device__ float  g_el2[Nn];
__device__ float  g_er2[Nn];

// ---------------- tf32 mma helpers ----------------
__device__ __forceinline__ uint32_t f2tf32(float f) {
    uint32_t r;
    asm("cvt.rna.tf32.f32 %0, %1;" : "=r"(r) : "f"(f));
    return r;
}

__device__ __forceinline__ void mma_tf32(float* d,
    uint32_t a0, uint32_t a1, uint32_t a2, uint32_t a3,
    uint32_t b0, uint32_t b1) {
    asm volatile(
        "mma.sync.aligned.m16n8k8.row.col.f32.tf32.tf32.f32 "
        "{%0,%1,%2,%3},{%4,%5,%6,%7},{%8,%9},{%0,%1,%2,%3};\n"
        : "+f"(d[0]), "+f"(d[1]), "+f"(d[2]), "+f"(d[3])
        : "r"(a0), "r"(a1), "r"(a2), "r"(a3), "r"(b0), "r"(b1));
}

// fp16 mma m16n8k16, fp32 accumulate
__device__ __forceinline__ void mma_f16(float* d,
    uint32_t a0, uint32_t a1, uint32_t a2, uint32_t a3,
    uint32_t b0, uint32_t b1) {
    asm volatile(
        "mma.sync.aligned.m16n8k16.row.col.f32.f16.f16.f32 "
        "{%0,%1,%2,%3},{%4,%5,%6,%7},{%8,%9},{%0,%1,%2,%3};\n"
        : "+f"(d[0]), "+f"(d[1]), "+f"(d[2]), "+f"(d[3])
        : "r"(a0), "r"(a1), "r"(a2), "r"(a3), "r"(b0), "r"(b1));
}

__device__ __forceinline__ void ldmatrix_x4_trans(uint32_t& r0, uint32_t& r1,
                                                  uint32_t& r2, uint32_t& r3,
                                                  uint32_t addr) {
    asm volatile("ldmatrix.sync.aligned.m8n8.x4.trans.shared.b16 {%0,%1,%2,%3}, [%4];"
        : "=r"(r0), "=r"(r1), "=r"(r2), "=r"(r3) : "r"(addr));
}

__device__ __forceinline__ float4 h4_to_f4(uint2 r) {
    __half2 p0 = *(__half2*)&r.x, p1 = *(__half2*)&r.y;
    return make_float4(__low2float(p0), __high2float(p0),
                       __low2float(p1), __high2float(p1));
}

// ---------------- zero / sentinel init ----------------
__global__ void k_zero() {
    int i = blockIdx.x * 256 + threadIdx.x;
    if (i < Nn + 1) g_rowptr[i] = 0;
    if (i < 64) { g_bsums[i] = -1; g_sflag[i] = 0; }
}

// ---------------- GEMM1 (tf32, fused: edge count + B prep + MMA) ----------------
#define S1P 100
__global__ void __launch_bounds__(256) k_gemm1(const float* __restrict__ x,
                                               const float* __restrict__ W1,
                                               const float* __restrict__ Wl1,
                                               const float* __restrict__ Wr1,
                                               const int* __restrict__ esrc) {
    extern __shared__ uint32_t sm1[];
    uint32_t* sB = sm1;                      // [128][S1P] pair-interleaved
    __shared__ float swl[F1 * H1], swr[F1 * H1];
    int tx = threadIdx.x, lane = tx & 31, w = tx >> 5;

    for (int e = blockIdx.x * 256 + tx; e < Ee; e += gridDim.x * 256)
        atomicAdd(&g_rowptr[esrc[e]], 1);

    for (int i = tx; i < FIN * F1; i += 256) {
        int k = i >> 5, n = i & 31;
        sB[(k >> 1) * S1P + 2 * n + (k & 1)] = f2tf32(W1[i]);
    }
    swl[tx] = Wl1[tx];
    swr[tx] = Wr1[tx];
    __syncthreads();

    {
        int k = tx;
        float sl[H1], sr[H1];
        #pragma unroll
        for (int h = 0; h < H1; h++) { sl[h] = 0.f; sr[h] = 0.f; }
        #pragma unroll 8
        for (int j = 0; j < F1; j++) {
            float v = __uint_as_float(sB[(k >> 1) * S1P + 2 * j + (k & 1)]);
            #pragma unroll
            for (int h = 0; h < H1; h++) {
                sl[h] = fmaf(v, swl[j * H1 + h], sl[h]);
                sr[h] = fmaf(v, swr[j * H1 + h], sr[h]);
            }
        }
        #pragma unroll
        for (int h = 0; h < H1; h++) {
            sB[(k >> 1) * S1P + 2 * (32 + h) + (k & 1)] = f2tf32(sl[h]);
            sB[(k >> 1) * S1P + 2 * (40 + h) + (k & 1)] = f2tf32(sr[h]);
        }
    }
    __syncthreads();

    int g = lane >> 2, c = lane & 3;
    int row0 = blockIdx.x * 128 + w * 16 + g;
    int row1 = row0 + 8;
    bool v0 = row0 < Nn, v1 = row1 < Nn;
    const float4* A0 = (const float4*)(x + (size_t)row0 * FIN);
    const float4* A1 = (const float4*)(x + (size_t)row1 * FIN);
    const float4 z4 = make_float4(0.f, 0.f, 0.f, 0.f);

    float acc[6][4];
    #pragma unroll
    for (int nt = 0; nt < 6; nt++)
        #pragma unroll
        for (int j = 0; j < 4; j++) acc[nt][j] = 0.f;

    float4 b0[4], b1[4];
    #pragma unroll
    for (int t = 0; t < 4; t++) {
        b0[t] = v0 ? A0[t * 4 + c] : z4;
        b1[t] = v1 ? A1[t * 4 + c] : z4;
    }
    #pragma unroll
    for (int ch = 0; ch < 4; ch++) {
        float4 n0[4], n1[4];
        #pragma unroll
        for (int t = 0; t < 4; t++) {
            n0[t] = (v0 && ch < 3) ? A0[(ch + 1) * 16 + t * 4 + c] : z4;
            n1[t] = (v1 && ch < 3) ? A1[(ch + 1) * 16 + t * 4 + c] : z4;
        }
        #pragma unroll
        for (int t = 0; t < 4; t++) {
            int wnd = ch * 4 + t;
            uint32_t a00 = f2tf32(b0[t].x), a01 = f2tf32(b0[t].y), a02 = f2tf32(b0[t].z), a03 = f2tf32(b0[t].w);
            uint32_t a10 = f2tf32(b1[t].x), a11 = f2tf32(b1[t].y), a12 = f2tf32(b1[t].z), a13 = f2tf32(b1[t].w);
            const uint32_t* bP = sB + (wnd * 8 + 2 * c) * S1P + 2 * g;
            #pragma unroll
            for (int nt = 0; nt < 6; nt++) {
                uint2 bb = *(const uint2*)(bP + 16 * nt);
                mma_tf32(acc[nt], a00, a10, a01, a11, bb.x, bb.y);
            }
            const uint32_t* bQ = bP + S1P;
            #pragma unroll
            for (int nt = 0; nt < 6; nt++) {
                uint2 bb = *(const uint2*)(bQ + 16 * nt);
                mma_tf32(acc[nt], a02, a12, a03, a13, bb.x, bb.y);
            }
        }
        #pragma unroll
        for (int t = 0; t < 4; t++) { b0[t] = n0[t]; b1[t] = n1[t]; }
    }
    #pragma unroll
    for (int nt = 0; nt < 4; nt++) {
        if (v0) ((__half2*)g_h1h)[(size_t)row0 * 16 + nt * 4 + c] = __floats2half2_rn(acc[nt][0], acc[nt][1]);
        if (v1) ((__half2*)g_h1h)[(size_t)row1 * 16 + nt * 4 + c] = __floats2half2_rn(acc[nt][2], acc[nt][3]);
    }
    if (v0) *(float2*)&g_el1[row0 * H1 + 2 * c] = make_float2(acc[4][0], acc[4][1]);
    if (v1) *(float2*)&g_el1[row1 * H1 + 2 * c] = make_float2(acc[4][2], acc[4][3]);
    if (v0) ((__half2*)g_er1h)[(size_t)row0 * 4 + c] = __floats2half2_rn(acc[5][0], acc[5][1]);
    if (v1) ((__half2*)g_er1h)[(size_t)row1 * 4 + c] = __floats2half2_rn(acc[5][2], acc[5][3]);
}

// ---------------- fused scan (decoupled lookback) + scatter ----------------
__global__ void k_scan_scatter(const int* __restrict__ src, const int* __restrict__ dst) {
    __shared__ int wsum[32];
    __shared__ int soff;
    int n = Nn + 1;
    int tid = threadIdx.x, b = blockIdx.x;
    int gid = b * 1024 + tid;
    int v = (gid < n) ? g_rowptr[gid] : 0;
    int lane = tid & 31, wid = tid >> 5;
    int x = v;
    #pragma unroll
    for (int d = 1; d < 32; d <<= 1) {
        int t = __shfl_up_sync(0xffffffffu, x, d);
        if (lane >= d) x += t;
    }
    if (lane == 31) wsum[wid] = x;
    __syncthreads();
    if (wid == 0) {
        int w = wsum[lane];
        #pragma unroll
        for (int d = 1; d < 32; d <<= 1) {
            int t = __shfl_up_sync(0xffffffffu, w, d);
            if (lane >= d) w += t;
        }
        wsum[lane] = w;
    }
    __syncthreads();
    int incl = x + (wid > 0 ? wsum[wid - 1] : 0);

    if (tid == 1023) atomicExch(&g_bsums[b], incl);

    if (tid < 32) {
        int p1 = 0, p2 = 0;
        if (tid < b)      { volatile int* p = &g_bsums[tid];      int u; do { u = *p; } while (u == -1); p1 = u; }
        if (tid + 32 < b) { volatile int* p = &g_bsums[tid + 32]; int u; do { u = *p; } while (u == -1); p2 = u; }
        int s = p1 + p2;
        #pragma unroll
        for (int d = 16; d > 0; d >>= 1) s += __shfl_xor_sync(0xffffffffu, s, d);
        if (tid == 0) soff = s;
    }
    __syncthreads();
    if (gid < n) {
        int val = soff + incl - v;
        g_rowptr[gid] = val;
        if (gid < Nn) g_cursor[gid] = val;
    }
    __threadfence();
    __syncthreads();
    if (tid == 0) atomicExch(&g_sflag[b], 1);

    if (tid < 49) { volatile int* p = &g_sflag[tid]; while (*p == 0) {} }
    __syncthreads();

    for (int e = b * 1024 + tid; e < Ee; e += 49 * 1024) {
        int s = src[e];
        int pos = atomicAdd(&g_cursor[s], 1);
        g_csr_dst[pos] = dst[e];
    }
}

// ---------------- layer-1 aggregation via fp16 tensor-core MMA ----------------
// Per 32-edge batch: acc[16(heads,8 pad)x32(feat)] += W[16x32] @ H[32x32].
// W^T stored in sW (edge-major, 8 halves/row), H rows in sH (32 halves + pad).
// ldmatrix .trans delivers exact a0/a1 (A) and b0/b1 (B) fragment layouts.
__global__ void __launch_bounds__(256) k_agg1(const float* __restrict__ b1) {
    __shared__ __half sH[8][32 * 40];   // [warp][edge*40 + feat], 80B rows
    __shared__ __half sW[8][32 * 8];    // [warp][edge*8 + head]
    __shared__ float  sD[8][32 * 9];    // den transpose buffer (stride 9)
    int wid = threadIdx.x >> 5, lane = threadIdx.x & 31;
    int i = blockIdx.x * 8 + wid;
    int gr = lane >> 2, tc = lane & 3;

    float el_own = (lane < H1) ? g_el1[i * H1 + lane] : 0.f;
    float elh[H1];
    #pragma unroll
    for (int h = 0; h < H1; h++) elh[h] = __shfl_sync(0xffffffffu, el_own, h);

    float denp[H1];
    #pragma unroll
    for (int h = 0; h < H1; h++) denp[h] = 0.f;
    float acc[4][4];
    #pragma unroll
    for (int nc = 0; nc < 4; nc++)
        #pragma unroll
        for (int j = 0; j < 4; j++) acc[nc][j] = 0.f;

    // ldmatrix shared addresses
    uint32_t aW = (uint32_t)__cvta_generic_to_shared(&sW[wid][lane * 8]);
    int eloc  = ((lane >> 3) & 1) * 8 + (lane & 7);   // edge within 16-group
    int fbase = (lane >> 4) * 8;                      // feat block 0/8
    uint32_t aH = (uint32_t)__cvta_generic_to_shared(&sH[wid][eloc * 40 + fbase]);
    uint32_t aStore = (uint32_t)0;  (void)aStore;

    int beg = g_rowptr[i], end = g_rowptr[i + 1];
    for (int base = beg; base < end; base += 32) {
        int nb = min(32, end - base);
        int dstl = (lane < nb) ? g_csr_dst[base + lane] : 0;

        // weights: exp(lrelu(el+er)) per head for this lane's edge
        float w_own[H1];
        if (lane < nb) {
            uint4 rv = *(const uint4*)(g_er1h + dstl * H1);
            __half2 e0 = *(__half2*)&rv.x, e1 = *(__half2*)&rv.y;
            __half2 e2 = *(__half2*)&rv.z, e3 = *(__half2*)&rv.w;
            float er_[H1] = {__low2float(e0), __high2float(e0), __low2float(e1), __high2float(e1),
                             __low2float(e2), __high2float(e2), __low2float(e3), __high2float(e3)};
            #pragma unroll
            for (int h = 0; h < H1; h++) {
                float a = elh[h] + er_[h];
                float lr = a > 0.f ? a : 0.2f * a;
                float wv = __expf(lr);
                w_own[h] = wv;
                denp[h] += wv;
            }
        } else {
            #pragma unroll
            for (int h = 0; h < H1; h++) w_own[h] = 0.f;
        }
        // pack weights -> sW row (16B)
        {
            uint4 wp;
            __half2 p0 = __floats2half2_rn(w_own[0], w_own[1]);
            __half2 p1 = __floats2half2_rn(w_own[2], w_own[3]);
            __half2 p2 = __floats2half2_rn(w_own[4], w_own[5]);
            __half2 p3 = __floats2half2_rn(w_own[6], w_own[7]);
            wp.x = *(uint32_t*)&p0; wp.y = *(uint32_t*)&p1;
            wp.z = *(uint32_t*)&p2; wp.w = *(uint32_t*)&p3;
            *(uint4*)&sW[wid][lane * 8] = wp;
        }
        // gather H row (64B) -> sH
        {
            const uint4* hr = (const uint4*)(g_h1h + dstl * F1);
            uint4 q0 = hr[0], q1 = hr[1], q2 = hr[2], q3 = hr[3];
            uint4* srow = (uint4*)&sH[wid][lane * 40];
            srow[0] = q0; srow[1] = q1; srow[2] = q2; srow[3] = q3;
        }
        __syncwarp();

        // A fragments: all 32 edges in one x4.trans (tiles: edges 0-7,8-15,16-23,24-31)
        uint32_t A0, A1, A2, A3;
        ldmatrix_x4_trans(A0, A1, A2, A3, aW);

        // k-chunk 0 (edges 0..15)
        uint32_t B0, B1, B2, B3;
        ldmatrix_x4_trans(B0, B1, B2, B3, aH);              // n-chunks 0,1
        mma_f16(acc[0], A0, 0u, A1, 0u, B0, B1);
        mma_f16(acc[1], A0, 0u, A1, 0u, B2, B3);
        ldmatrix_x4_trans(B0, B1, B2, B3, aH + 32);         // n-chunks 2,3
        mma_f16(acc[2], A0, 0u, A1, 0u, B0, B1);
        mma_f16(acc[3], A0, 0u, A1, 0u, B2, B3);

        if (nb > 16) {  // k-chunk 1 (edges 16..31)
            ldmatrix_x4_trans(B0, B1, B2, B3, aH + 1280);
            mma_f16(acc[0], A2, 0u, A3, 0u, B0, B1);
            mma_f16(acc[1], A2, 0u, A3, 0u, B2, B3);
            ldmatrix_x4_trans(B0, B1, B2, B3, aH + 1280 + 32);
            mma_f16(acc[2], A2, 0u, A3, 0u, B0, B1);
            mma_f16(acc[3], A2, 0u, A3, 0u, B2, B3);
        }
        __syncwarp();
    }

    // denominator: transpose-reduce via smem (stride 9: conflict-free)
    #pragma unroll
    for (int h = 0; h < H1; h++) sD[wid][lane * 9 + h] = denp[h];
    __syncwarp();
    float part = 0.f;
    #pragma unroll
    for (int m = 0; m < 8; m++) part += sD[wid][(tc * 8 + m) * 9 + gr];
    part += __shfl_xor_sync(0xffffffffu, part, 1);
    part += __shfl_xor_sync(0xffffffffu, part, 2);
    float rden = __fdividef(1.f, fmaxf(part, 1e-12f));

    // epilogue: lane (gr,tc) holds head gr, feats nc*8+2tc, +1
    __half2* r1h2 = (__half2*)g_r1h;
    #pragma unroll
    for (int nc = 0; nc < 4; nc++) {
        float2 bb = ((const float2*)b1)[nc * 4 + tc];
        float o0 = fmaf(acc[nc][0], rden, bb.x);
        float o1 = fmaf(acc[nc][1], rden, bb.y);
        float e0 = o0 > 0.f ? o0 : (__expf(o0) - 1.f);
        float e1 = o1 > 0.f ? o1 : (__expf(o1) - 1.f);
        r1h2[i * 128 + gr * 16 + nc * 4 + tc] = __floats2half2_rn(e0, e1);
    }
}

// ---------------- GEMM2 (tf32, fused B prep, fp16 A from r1h) ----------------
#define S2P 116
__global__ void __launch_bounds__(256) k_gemm2(const float* __restrict__ W2,
                                               const float* __restrict__ Wl2,
                                               const float* __restrict__ Wr2) {
    extern __shared__ uint32_t sm2[];
    uint32_t* sB = sm2;                      // [128][S2P]
    __shared__ float swl2[NC], swr2[NC];
    int tx = threadIdx.x, lane = tx & 31, w = tx >> 5;
    if (tx < NC) { swl2[tx] = Wl2[tx]; swr2[tx] = Wr2[tx]; }
    __syncthreads();
    {
        int k = tx;
        float sl = 0.f, sr = 0.f;
        #pragma unroll 4
        for (int j = 0; j < NC; j++) {
            float v = W2[k * NC + j];
            sB[(k >> 1) * S2P + 2 * j + (k & 1)] = f2tf32(v);
            sl = fmaf(v, swl2[j], sl);
            sr = fmaf(v, swr2[j], sr);
        }
        sB[(k >> 1) * S2P + 2 * 47 + (k & 1)] = 0u;
        sB[(k >> 1) * S2P + 2 * 48 + (k & 1)] = f2tf32(sl);
        sB[(k >> 1) * S2P + 2 * 49 + (k & 1)] = f2tf32(sr);
        #pragma unroll
        for (int j = 50; j < 56; j++) sB[(k >> 1) * S2P + 2 * j + (k & 1)] = 0u;
    }
    __syncthreads();

    int g = lane >> 2, c = lane & 3;
    int row0 = blockIdx.x * 128 + w * 16 + g;
    int row1 = row0 + 8;
    bool v0 = row0 < Nn, v1 = row1 < Nn;
    const uint2* A0 = (const uint2*)(g_r1h + (size_t)row0 * FIN);
    const uint2* A1 = (const uint2*)(g_r1h + (size_t)row1 * FIN);
    const uint2 z2 = make_uint2(0u, 0u);

    float acc[7][4];
    #pragma unroll
    for (int nt = 0; nt < 7; nt++)
        #pragma unroll
        for (int j = 0; j < 4; j++) acc[nt][j] = 0.f;

    uint2 b0[4], b1[4];
    #pragma unroll
    for (int t = 0; t < 4; t++) {
        b0[t] = v0 ? A0[t * 4 + c] : z2;
        b1[t] = v1 ? A1[t * 4 + c] : z2;
    }
    #pragma unroll
    for (int ch = 0; ch < 4; ch++) {
        uint2 n0[4], n1[4];
        #pragma unroll
        for (int t = 0; t < 4; t++) {
            n0[t] = (v0 && ch < 3) ? A0[(ch + 1) * 16 + t * 4 + c] : z2;
            n1[t] = (v1 && ch < 3) ? A1[(ch + 1) * 16 + t * 4 + c] : z2;
        }
        #pragma unroll
        for (int t = 0; t < 4; t++) {
            int wnd = ch * 4 + t;
            float4 fa0 = h4_to_f4(b0[t]);
            float4 fa1 = h4_to_f4(b1[t]);
            uint32_t a00 = f2tf32(fa0.x), a01 = f2tf32(fa0.y), a02 = f2tf32(fa0.z), a03 = f2tf32(fa0.w);
            uint32_t a10 = f2tf32(fa1.x), a11 = f2tf32(fa1.y), a12 = f2tf32(fa1.z), a13 = f2tf32(fa1.w);
            const uint32_t* bP = sB + (wnd * 8 + 2 * c) * S2P + 2 * g;
            #pragma unroll
            for (int nt = 0; nt < 7; nt++) {
                uint2 bb = *(const uint2*)(bP + 16 * nt);
                mma_tf32(acc[nt], a00, a10, a01, a11, bb.x, bb.y);
            }
            const uint32_t* bQ = bP + S2P;
            #pragma unroll
            for (int nt = 0; nt < 7; nt++) {
                uint2 bb = *(const uint2*)(bQ + 16 * nt);
                mma_tf32(acc[nt], a02, a12, a03, a13, bb.x, bb.y);
            }
        }
        #pragma unroll
        for (int t = 0; t < 4; t++) { b0[t] = n0[t]; b1[t] = n1[t]; }
    }
    #pragma unroll
    for (int nt = 0; nt < 7; nt++) {
        int col = nt * 8 + 2 * c;
        if (col < 48) {
            if (v0) ((__half2*)g_h2ph)[(size_t)row0 * 24 + nt * 4 + c] = __floats2half2_rn(acc[nt][0], acc[nt][1]);
            if (v1) ((__half2*)g_h2ph)[(size_t)row1 * 24 + nt * 4 + c] = __floats2half2_rn(acc[nt][2], acc[nt][3]);
        } else if (col == 48) {
            if (v0) { g_el2[row0] = acc[nt][0]; g_er2[row0] = acc[nt][1]; }
            if (v1) { g_el2[row1] = acc[nt][2]; g_er2[row1] = acc[nt][3]; }
        }
    }
}

// ---------------- layer-2 aggregation (fp16 gathers) + log_softmax ----------------
__global__ void __launch_bounds__(256) k_agg2(const float* __restrict__ b2, float* __restrict__ out) {
    int wid = threadIdx.x >> 5, lane = threadIdx.x & 31;
    int i = blockIdx.x * 8 + wid;
    float el = g_el2[i];
    float accx = 0.f, accy = 0.f, denp = 0.f;
    int beg = g_rowptr[i], end = g_rowptr[i + 1];
    const __half2* __restrict__ h2p2 = (const __half2*)g_h2ph;
    for (int base = beg; base < end; base += 32) {
        int nb = min(32, end - base);
        int dstl = (lane < nb) ? g_csr_dst[base + lane] : 0;
        float wl_ = 0.f;
        if (lane < nb) {
            float a = el + g_er2[dstl];
            float lr = a > 0.f ? a : 0.2f * a;
            wl_ = __expf(lr);
            denp += wl_;
        }
        for (int j = 0; j < nb; j += 8) {
            int dd[8];
            float wv[8];
            #pragma unroll
            for (int u = 0; u < 8; u++) {
                dd[u] = __shfl_sync(0xffffffffu, dstl, j + u);
                wv[u] = __shfl_sync(0xffffffffu, wl_, j + u);
            }
            if (lane < 24) {
                __half2 hh[8];
                #pragma unroll
                for (int u = 0; u < 8; u++)
                    hh[u] = h2p2[dd[u] * 24 + lane];
                #pragma unroll
                for (int u = 0; u < 8; u++) {
                    accx = fmaf(wv[u], __low2float(hh[u]), accx);
                    accy = fmaf(wv[u], __high2float(hh[u]), accy);
                }
            }
        }
    }
    float den = denp;
    #pragma unroll
    for (int d = 16; d > 0; d >>= 1) den += __shfl_xor_sync(0xffffffffu, den, d);
    float rden = __fdividef(1.f, fmaxf(den, 1e-12f));
    float vx = -3.0e38f, vy = -3.0e38f;
    if (lane < 24) {
        vx = fmaf(accx, rden, b2[2 * lane]);
        vy = (2 * lane + 1 < NC) ? fmaf(accy, rden, b2[2 * lane + 1]) : -3.0e38f;
    }
    float m = fmaxf(vx, vy);
    #pragma unroll
    for (int d = 16; d > 0; d >>= 1) m = fmaxf(m, __shfl_xor_sync(0xffffffffu, m, d));
    float s = 0.f;
    if (lane < 24) {
        s = __expf(vx - m);
        if (2 * lane + 1 < NC) s += __expf(vy - m);
    }
    #pragma unroll
    for (int d = 16; d > 0; d >>= 1) s += __shfl_xor_sync(0xffffffffu, s, d);
    float ls = logf(s);
    if (lane < 24) {
        out[(size_t)i * NC + 2 * lane] = vx - m - ls;
        if (2 * lane + 1 < NC) out[(size_t)i * NC + 2 * lane + 1] = vy - m - ls;
    }
}

// ---------------- launch (6 kernels; #4 = k_agg1 -> profiled) ----------------
extern "C" void kernel_launch(void* const* d_in, const int* in_sizes, int n_in,
                              void* d_out, int out_size) {
    const float* x    = (const float*)d_in[0];
    const int*   esrc = (const int*)  d_in[1];
    const int*   edst = (const int*)  d_in[2];
    const float* W1   = (const float*)d_in[3];
    const float* Wl1  = (const float*)d_in[4];
    const float* Wr1  = (const float*)d_in[5];
    const float* b1   = (const float*)d_in[6];
    const float* W2   = (const float*)d_in[7];
    const float* Wl2  = (const float*)d_in[8];
    const float* Wr2  = (const float*)d_in[9];
    const float* b2   = (const float*)d_in[10];
    float* out = (float*)d_out;

    const int smem1 = 128 * S1P * 4;   // 51.2 KB
    const int smem2 = 128 * S2P * 4;   // 59.4 KB
    cudaFuncSetAttribute(k_gemm1, cudaFuncAttributeMaxDynamicSharedMemorySize, smem1);
    cudaFuncSetAttribute(k_gemm2, cudaFuncAttributeMaxDynamicSharedMemorySize, smem2);

    k_zero<<<(Nn + 1 + 255) / 256, 256>>>();
    k_gemm1<<<(Nn + 127) / 128, 256, smem1>>>(x, W1, Wl1, Wr1, esrc);
    k_scan_scatter<<<49, 1024>>>(esrc, edst);
    k_agg1<<<Nn / 8, 256>>>(b1);                    // #4 <- profiled
    k_gemm2<<<(Nn + 127) / 128, 256, smem2>>>(W2, Wl2, Wr2);
    k_agg2<<<Nn / 8, 256>>>(b2, out);
}